// round 1
// baseline (speedup 1.0000x reference)
#include <cuda_runtime.h>
#include <cuda_bf16.h>
#include <math.h>
#include <stdint.h>

// Shapes (fixed per reference)
#define BB 4
#define NN 1024
#define NC 77
#define DD 1024
#define HH 16
#define HD 64
#define DFF 4096
#define S_TOT (NN + NC)        // 1101
#define XROWS (BB * NN)        // 4096
#define CROWS (BB * NC)        // 308
#define TROWS (XROWS + CROWS)  // 4404

// ---------------- scratch (device globals; no allocation allowed) ----------------
__device__ float g_adaA[BB * 6 * DD];        // [4][6144]
__device__ float g_adaC[BB * 6 * DD];
__device__ float g_xt[TROWS * DD];           // modulated activations (both LN passes)
__device__ float g_qkvx[XROWS * 3 * DD];     // [row][3*1024]: q|k|v each [H][hd]
__device__ float g_qkvc[CROWS * 3 * DD];
__device__ float g_attn[TROWS * DD];         // attention output, [token][h*hd]
__device__ float g_xmid[XROWS * DD];         // x after MSA residual
__device__ float g_cmid[CROWS * DD];
__device__ float g_hx[XROWS * DFF];          // MLP hidden
__device__ float g_hc[CROWS * DFF];

// ---------------- helpers ----------------
__device__ __forceinline__ float gelu_tanh(float x) {
    float x3 = x * x * x;
    float t = tanhf(0.7978845608028654f * (x + 0.044715f * x3));
    return 0.5f * x * (1.0f + t);
}

// ---------------- adaLN: sc = silu(c); ada = sc @ W + b for both streams -------
// grid (6144/256, 2), block 256. Each block computes 256 columns for all 4 batches.
__global__ void ada_kernel(const float* __restrict__ c,
                           const float* __restrict__ Wa, const float* __restrict__ ba,
                           const float* __restrict__ Wc, const float* __restrict__ bc,
                           float* __restrict__ outA, float* __restrict__ outC) {
    __shared__ float scs[BB * DD];
    int tid = threadIdx.x;
    for (int idx = tid; idx < BB * DD; idx += 256) {
        float v = c[idx];
        scs[idx] = v / (1.0f + __expf(-v));
    }
    __syncthreads();
    const float* W = blockIdx.y ? Wc : Wa;
    const float* bias = blockIdx.y ? bc : ba;
    float* out = blockIdx.y ? outC : outA;
    int col = blockIdx.x * 256 + tid;
    float a0 = 0.f, a1 = 0.f, a2 = 0.f, a3 = 0.f;
    for (int k = 0; k < DD; k++) {
        float w = __ldg(&W[(size_t)k * 6144 + col]);
        a0 += scs[k] * w;
        a1 += scs[DD + k] * w;
        a2 += scs[2 * DD + k] * w;
        a3 += scs[3 * DD + k] * w;
    }
    float bv = bias[col];
    out[col] = a0 + bv;
    out[6144 + col] = a1 + bv;
    out[2 * 6144 + col] = a2 + bv;
    out[3 * 6144 + col] = a3 + bv;
}

// ---------------- LayerNorm + modulate -------------------------------------------
// grid 4404 blocks (x rows then cond rows), block 256. shift at ada[ofs], scale at ada[ofs+1024]
__global__ void ln_mod_kernel(const float* __restrict__ xs, const float* __restrict__ cs,
                              const float* __restrict__ adaA, const float* __restrict__ adaC,
                              int sofs, float* __restrict__ out) {
    int r = blockIdx.x;
    int tid = threadIdx.x;
    const float* src;
    const float* ada;
    int b;
    if (r < XROWS) { b = r >> 10; src = xs + (size_t)r * DD; ada = adaA; }
    else { int rc = r - XROWS; b = rc / NC; src = cs + (size_t)rc * DD; ada = adaC; }

    float4 v = *(const float4*)(src + tid * 4);
    float s = v.x + v.y + v.z + v.w;
    float sq = v.x * v.x + v.y * v.y + v.z * v.z + v.w * v.w;
    #pragma unroll
    for (int o = 16; o; o >>= 1) {
        s += __shfl_xor_sync(0xffffffffu, s, o);
        sq += __shfl_xor_sync(0xffffffffu, sq, o);
    }
    __shared__ float rs[8], rq[8];
    __shared__ float smu, srstd;
    int w = tid >> 5;
    if ((tid & 31) == 0) { rs[w] = s; rq[w] = sq; }
    __syncthreads();
    if (tid == 0) {
        float ts = 0.f, tq = 0.f;
        #pragma unroll
        for (int i = 0; i < 8; i++) { ts += rs[i]; tq += rq[i]; }
        float mu = ts * (1.0f / DD);
        float var = tq * (1.0f / DD) - mu * mu;
        smu = mu;
        srstd = rsqrtf(var + 1e-6f);
    }
    __syncthreads();
    float mu = smu, rstd = srstd;
    const float* ap = ada + (size_t)b * 6144 + sofs;
    int col = tid * 4;
    float4 sh = *(const float4*)(ap + col);
    float4 sc = *(const float4*)(ap + 1024 + col);
    float4 o;
    o.x = (v.x - mu) * rstd * (1.0f + sc.x) + sh.x;
    o.y = (v.y - mu) * rstd * (1.0f + sc.y) + sh.y;
    o.z = (v.z - mu) * rstd * (1.0f + sc.z) + sh.z;
    o.w = (v.w - mu) * rstd * (1.0f + sc.w) + sh.w;
    *(float4*)(out + (size_t)r * DD + col) = o;
}

// ---------------- generic SGEMM: C = epi(A @ B + bias) ---------------------------
// 128x128x8 tiles, 256 threads, 8x8 per-thread micro-tile, register prefetch.
// mode 0: none, 1: GELU, 2: C = res + gate * (acc+bias)
__global__ __launch_bounds__(256, 2) void sgemm_kernel(
    const float* __restrict__ A, const float* __restrict__ B, const float* __restrict__ bias,
    float* __restrict__ C, int M, int N, int K,
    const float* __restrict__ res, const float* __restrict__ gate, int gofs, int rpb, int mode) {
    __shared__ float As[8][128];
    __shared__ float Bs[8][128];
    const int tid = threadIdx.x;
    const int row0 = blockIdx.y * 128, col0 = blockIdx.x * 128;
    const int tr = (tid >> 4) * 8, tc = (tid & 15) * 8;
    const int ar = tid >> 1, ac = (tid & 1) * 4;
    const int br = tid >> 5, bc = (tid & 31) * 4;
    const float* Ap = A + (size_t)(row0 + ar) * K + ac;
    const float* Bp = B + (size_t)br * N + col0 + bc;
    const bool aval = (row0 + ar) < M;

    float4 arg = make_float4(0.f, 0.f, 0.f, 0.f);
    if (aval) arg = *(const float4*)Ap;
    float4 brg = *(const float4*)Bp;

    float acc[8][8];
    #pragma unroll
    for (int i = 0; i < 8; i++)
        #pragma unroll
        for (int j = 0; j < 8; j++) acc[i][j] = 0.f;

    const int nt = K >> 3;
    int t = 0;
    for (;;) {
        As[ac + 0][ar] = arg.x;
        As[ac + 1][ar] = arg.y;
        As[ac + 2][ar] = arg.z;
        As[ac + 3][ar] = arg.w;
        *(float4*)&Bs[br][bc] = brg;
        __syncthreads();
        t++;
        if (t < nt) {
            if (aval) arg = *(const float4*)(Ap + (size_t)t * 8);
            brg = *(const float4*)(Bp + (size_t)t * 8 * N);
        }
        #pragma unroll
        for (int k = 0; k < 8; k++) {
            float ra[8], rb[8];
            *(float4*)&ra[0] = *(const float4*)&As[k][tr];
            *(float4*)&ra[4] = *(const float4*)&As[k][tr + 4];
            *(float4*)&rb[0] = *(const float4*)&Bs[k][tc];
            *(float4*)&rb[4] = *(const float4*)&Bs[k][tc + 4];
            #pragma unroll
            for (int i = 0; i < 8; i++)
                #pragma unroll
                for (int j = 0; j < 8; j++) acc[i][j] += ra[i] * rb[j];
        }
        if (t >= nt) break;
        __syncthreads();
    }

    #pragma unroll
    for (int i = 0; i < 8; i++) {
        int r = row0 + tr + i;
        if (r >= M) break;
        #pragma unroll
        for (int j = 0; j < 8; j += 4) {
            int cc = col0 + tc + j;
            float4 bv = *(const float4*)&bias[cc];
            float4 o;
            o.x = acc[i][j + 0] + bv.x;
            o.y = acc[i][j + 1] + bv.y;
            o.z = acc[i][j + 2] + bv.z;
            o.w = acc[i][j + 3] + bv.w;
            if (mode == 1) {
                o.x = gelu_tanh(o.x); o.y = gelu_tanh(o.y);
                o.z = gelu_tanh(o.z); o.w = gelu_tanh(o.w);
            } else if (mode == 2) {
                int bb = r / rpb;
                float4 g = *(const float4*)&gate[(size_t)bb * 6144 + gofs + cc];
                float4 rr = *(const float4*)&res[(size_t)r * N + cc];
                o.x = rr.x + g.x * o.x;
                o.y = rr.y + g.y * o.y;
                o.z = rr.z + g.z * o.z;
                o.w = rr.w + g.w * o.w;
            }
            *(float4*)&C[(size_t)r * N + cc] = o;
        }
    }
}

// ---------------- joint flash attention ------------------------------------------
// grid (ceil(1101/64)=18, H=16, B=4), block 256 (ty=tid/16 -> 4 q-rows, tx=tid%16).
// Q in smem [qr][d]; K stored transposed [d][kr]; P overwrites K buffer. 48KB static.
__global__ __launch_bounds__(256) void attn_kernel(const float* __restrict__ qkvx,
                                                   const float* __restrict__ qkvc,
                                                   float* __restrict__ out) {
    __shared__ float Qs[64 * 64];
    __shared__ float KP[64 * 64];
    __shared__ float Vs[64 * 64];
    const int qt = blockIdx.x, h = blockIdx.y, b = blockIdx.z;
    const int tid = threadIdx.x;
    const int ty = tid >> 4, tx = tid & 15;
    const int q0 = qt * 64;

    // load Q tile (scaled by hd^-0.5 = 0.125)
    #pragma unroll
    for (int rep = 0; rep < 4; rep++) {
        int lin = rep * 256 + tid;      // float4 index
        int qr = lin >> 4;
        int d4 = (lin & 15) * 4;
        int qi = q0 + qr;
        float4 v = make_float4(0.f, 0.f, 0.f, 0.f);
        if (qi < S_TOT) {
            const float* rp = (qi < NN) ? (qkvx + (size_t)(b * NN + qi) * 3072)
                                        : (qkvc + (size_t)(b * NC + (qi - NN)) * 3072);
            v = *(const float4*)(rp + h * HD + d4);
        }
        v.x *= 0.125f; v.y *= 0.125f; v.z *= 0.125f; v.w *= 0.125f;
        *(float4*)&Qs[qr * 64 + d4] = v;
    }

    float o[4][4];
    float m[4], l[4];
    #pragma unroll
    for (int i = 0; i < 4; i++) {
        m[i] = -1e30f; l[i] = 0.f;
        #pragma unroll
        for (int j = 0; j < 4; j++) o[i][j] = 0.f;
    }

    const int nkt = (S_TOT + 63) / 64;  // 18
    for (int kt = 0; kt < nkt; kt++) {
        __syncthreads();  // prior-iter P/V reads done (also covers Q writes at kt=0)
        // load K (transposed into KP) and V
        #pragma unroll
        for (int rep = 0; rep < 4; rep++) {
            int lin = rep * 256 + tid;
            int kr = lin >> 4;
            int d4 = (lin & 15) * 4;
            int ki = kt * 64 + kr;
            float4 kv = make_float4(0.f, 0.f, 0.f, 0.f);
            float4 vv = make_float4(0.f, 0.f, 0.f, 0.f);
            if (ki < S_TOT) {
                const float* rp = (ki < NN) ? (qkvx + (size_t)(b * NN + ki) * 3072)
                                            : (qkvc + (size_t)(b * NC + (ki - NN)) * 3072);
                kv = *(const float4*)(rp + 1024 + h * HD + d4);
                vv = *(const float4*)(rp + 2048 + h * HD + d4);
            }
            KP[(d4 + 0) * 64 + kr] = kv.x;
            KP[(d4 + 1) * 64 + kr] = kv.y;
            KP[(d4 + 2) * 64 + kr] = kv.z;
            KP[(d4 + 3) * 64 + kr] = kv.w;
            *(float4*)&Vs[kr * 64 + d4] = vv;
        }
        __syncthreads();

        // scores s[4][4] = Q[ty*4+i] . K[tx*4+j]
        float s[4][4];
        #pragma unroll
        for (int i = 0; i < 4; i++)
            #pragma unroll
            for (int j = 0; j < 4; j++) s[i][j] = 0.f;
        #pragma unroll
        for (int d4 = 0; d4 < 64; d4 += 4) {
            float4 qv[4];
            #pragma unroll
            for (int i = 0; i < 4; i++) qv[i] = *(const float4*)&Qs[(ty * 4 + i) * 64 + d4];
            #pragma unroll
            for (int dd = 0; dd < 4; dd++) {
                float4 kv4 = *(const float4*)&KP[(d4 + dd) * 64 + tx * 4];
                #pragma unroll
                for (int i = 0; i < 4; i++) {
                    float qd = ((const float*)&qv[i])[dd];
                    s[i][0] += qd * kv4.x;
                    s[i][1] += qd * kv4.y;
                    s[i][2] += qd * kv4.z;
                    s[i][3] += qd * kv4.w;
                }
            }
        }
        // mask invalid keys
        #pragma unroll
        for (int j = 0; j < 4; j++) {
            if (kt * 64 + tx * 4 + j >= S_TOT) {
                #pragma unroll
                for (int i = 0; i < 4; i++) s[i][j] = -1e30f;
            }
        }
        // online softmax update (row reduce over the 16-lane tx group)
        #pragma unroll
        for (int i = 0; i < 4; i++) {
            float tm = fmaxf(fmaxf(s[i][0], s[i][1]), fmaxf(s[i][2], s[i][3]));
            #pragma unroll
            for (int off = 1; off < 16; off <<= 1)
                tm = fmaxf(tm, __shfl_xor_sync(0xffffffffu, tm, off));
            float mn = fmaxf(m[i], tm);
            float sc = __expf(m[i] - mn);
            float tl = 0.f;
            #pragma unroll
            for (int j = 0; j < 4; j++) {
                float p = __expf(s[i][j] - mn);
                s[i][j] = p;
                tl += p;
            }
            #pragma unroll
            for (int off = 1; off < 16; off <<= 1)
                tl += __shfl_xor_sync(0xffffffffu, tl, off);
            l[i] = l[i] * sc + tl;
            m[i] = mn;
            #pragma unroll
            for (int j = 0; j < 4; j++) o[i][j] *= sc;
        }
        __syncthreads();  // everyone done reading K before P overwrites it
        #pragma unroll
        for (int i = 0; i < 4; i++)
            *(float4*)&KP[(ty * 4 + i) * 64 + tx * 4] =
                make_float4(s[i][0], s[i][1], s[i][2], s[i][3]);
        __syncthreads();
        // O += P @ V  (o cols = tx*4..tx*4+3)
        #pragma unroll
        for (int k4 = 0; k4 < 64; k4 += 4) {
            float4 pv[4];
            #pragma unroll
            for (int i = 0; i < 4; i++) pv[i] = *(const float4*)&KP[(ty * 4 + i) * 64 + k4];
            #pragma unroll
            for (int kk = 0; kk < 4; kk++) {
                float4 vv = *(const float4*)&Vs[(k4 + kk) * 64 + tx * 4];
                #pragma unroll
                for (int i = 0; i < 4; i++) {
                    float p = ((const float*)&pv[i])[kk];
                    o[i][0] += p * vv.x;
                    o[i][1] += p * vv.y;
                    o[i][2] += p * vv.z;
                    o[i][3] += p * vv.w;
                }
            }
        }
    }

    // write out
    #pragma unroll
    for (int i = 0; i < 4; i++) {
        int qi = q0 + ty * 4 + i;
        if (qi >= S_TOT) continue;
        int rowg = (qi < NN) ? (b * NN + qi) : (XROWS + b * NC + (qi - NN));
        float inv = 1.0f / l[i];
        float4 ov = make_float4(o[i][0] * inv, o[i][1] * inv, o[i][2] * inv, o[i][3] * inv);
        *(float4*)&out[(size_t)rowg * DD + h * HD + tx * 4] = ov;
    }
}

// ---------------- launcher ----------------
extern "C" void kernel_launch(void* const* d_in, const int* in_sizes, int n_in,
                              void* d_out, int out_size) {
    const float* x       = (const float*)d_in[0];
    const float* cond    = (const float*)d_in[1];
    const float* c       = (const float*)d_in[2];
    const float* W_ada   = (const float*)d_in[3];
    const float* b_ada   = (const float*)d_in[4];
    const float* W_ada_c = (const float*)d_in[5];
    const float* b_ada_c = (const float*)d_in[6];
    const float* W_qkv   = (const float*)d_in[7];
    const float* b_qkv   = (const float*)d_in[8];
    const float* W_proj  = (const float*)d_in[9];
    const float* b_proj  = (const float*)d_in[10];
    const float* W_qkv_c = (const float*)d_in[11];
    const float* b_qkv_c = (const float*)d_in[12];
    const float* W_proj_c= (const float*)d_in[13];
    const float* b_proj_c= (const float*)d_in[14];
    const float* W_fc1   = (const float*)d_in[15];
    const float* b_fc1   = (const float*)d_in[16];
    const float* W_fc2   = (const float*)d_in[17];
    const float* b_fc2   = (const float*)d_in[18];
    const float* W_fc1_c = (const float*)d_in[19];
    const float* b_fc1_c = (const float*)d_in[20];
    const float* W_fc2_c = (const float*)d_in[21];
    const float* b_fc2_c = (const float*)d_in[22];
    float* out = (float*)d_out;

    float *adaA, *adaC, *xt, *qkvx, *qkvc, *attn, *xmid, *cmid, *hx, *hc;
    cudaGetSymbolAddress((void**)&adaA, g_adaA);
    cudaGetSymbolAddress((void**)&adaC, g_adaC);
    cudaGetSymbolAddress((void**)&xt,   g_xt);
    cudaGetSymbolAddress((void**)&qkvx, g_qkvx);
    cudaGetSymbolAddress((void**)&qkvc, g_qkvc);
    cudaGetSymbolAddress((void**)&attn, g_attn);
    cudaGetSymbolAddress((void**)&xmid, g_xmid);
    cudaGetSymbolAddress((void**)&cmid, g_cmid);
    cudaGetSymbolAddress((void**)&hx,   g_hx);
    cudaGetSymbolAddress((void**)&hc,   g_hc);

    // 1. adaLN
    ada_kernel<<<dim3(6144 / 256, 2), 256>>>(c, W_ada, b_ada, W_ada_c, b_ada_c, adaA, adaC);
    // 2. LN + modulate (MSA): shift ofs 0, scale ofs 1024
    ln_mod_kernel<<<TROWS, 256>>>(x, cond, adaA, adaC, 0, xt);
    // 3. QKV GEMMs
    sgemm_kernel<<<dim3(3072 / 128, XROWS / 128), 256>>>(xt, W_qkv, b_qkv, qkvx,
        XROWS, 3072, 1024, nullptr, nullptr, 0, 1, 0);
    sgemm_kernel<<<dim3(3072 / 128, (CROWS + 127) / 128), 256>>>(xt + (size_t)XROWS * DD,
        W_qkv_c, b_qkv_c, qkvc, CROWS, 3072, 1024, nullptr, nullptr, 0, 1, 0);
    // 4. joint attention
    attn_kernel<<<dim3((S_TOT + 63) / 64, HH, BB), 256>>>(qkvx, qkvc, attn);
    // 5. proj + gated residual -> x_mid / c_mid
    sgemm_kernel<<<dim3(1024 / 128, XROWS / 128), 256>>>(attn, W_proj, b_proj, xmid,
        XROWS, 1024, 1024, x, adaA, 2048, NN, 2);
    sgemm_kernel<<<dim3(1024 / 128, (CROWS + 127) / 128), 256>>>(attn + (size_t)XROWS * DD,
        W_proj_c, b_proj_c, cmid, CROWS, 1024, 1024, cond, adaC, 2048, NC, 2);
    // 6. LN + modulate (MLP): shift ofs 3072, scale ofs 4096
    ln_mod_kernel<<<TROWS, 256>>>(xmid, cmid, adaA, adaC, 3072, xt);
    // 7. fc1 + GELU
    sgemm_kernel<<<dim3(DFF / 128, XROWS / 128), 256>>>(xt, W_fc1, b_fc1, hx,
        XROWS, DFF, 1024, nullptr, nullptr, 0, 1, 1);
    sgemm_kernel<<<dim3(DFF / 128, (CROWS + 127) / 128), 256>>>(xt + (size_t)XROWS * DD,
        W_fc1_c, b_fc1_c, hc, CROWS, DFF, 1024, nullptr, nullptr, 0, 1, 1);
    // 8. fc2 + gated residual -> final outputs directly into d_out
    sgemm_kernel<<<dim3(1024 / 128, XROWS / 128), 256>>>(hx, W_fc2, b_fc2, out,
        XROWS, 1024, DFF, xmid, adaA, 5120, NN, 2);
    sgemm_kernel<<<dim3(1024 / 128, (CROWS + 127) / 128), 256>>>(hc, W_fc2_c, b_fc2_c,
        out + (size_t)XROWS * DD, CROWS, 1024, DFF, cmid, adaC, 5120, NC, 2);
}

// round 2
// speedup vs baseline: 2.3026x; 2.3026x over previous
#include <cuda_runtime.h>
#include <cuda_bf16.h>
#include <math.h>
#include <stdint.h>

// Shapes (fixed per reference)
#define BB 4
#define NN 1024
#define NC 77
#define DD 1024
#define HH 16
#define HD 64
#define DFF 4096
#define S_TOT (NN + NC)        // 1101
#define XROWS (BB * NN)        // 4096
#define CROWS (BB * NC)        // 308
#define TROWS (XROWS + CROWS)  // 4404

// ---------------- scratch (device globals; no allocation allowed) ----------------
__device__ float g_adaA[BB * 6 * DD];
__device__ float g_adaC[BB * 6 * DD];
__device__ float g_xt[TROWS * DD];
__device__ float g_qkvx[XROWS * 3 * DD];
__device__ float g_qkvc[CROWS * 3 * DD];
__device__ float g_attn[TROWS * DD];
__device__ float g_xmid[XROWS * DD];
__device__ float g_cmid[CROWS * DD];
__device__ float g_hx[XROWS * DFF];
__device__ float g_hc[CROWS * DFF];

// ---------------- helpers ----------------
__device__ __forceinline__ float gelu_tanh(float x) {
    float x3 = x * x * x;
    float t = tanhf(0.7978845608028654f * (x + 0.044715f * x3));
    return 0.5f * x * (1.0f + t);
}

__device__ __forceinline__ uint32_t f2tf(float f) {
    uint32_t r;
    asm("cvt.rna.tf32.f32 %0, %1;" : "=r"(r) : "f"(f));
    return r;
}

__device__ __forceinline__ void mma_tf32(float& c0, float& c1, float& c2, float& c3,
                                         uint32_t a0, uint32_t a1, uint32_t a2, uint32_t a3,
                                         uint32_t b0, uint32_t b1) {
    asm volatile("mma.sync.aligned.m16n8k8.row.col.f32.tf32.tf32.f32 "
                 "{%0,%1,%2,%3}, {%4,%5,%6,%7}, {%8,%9}, {%0,%1,%2,%3};"
                 : "+f"(c0), "+f"(c1), "+f"(c2), "+f"(c3)
                 : "r"(a0), "r"(a1), "r"(a2), "r"(a3), "r"(b0), "r"(b1));
}

__device__ __forceinline__ void cp16(void* sm, const void* g, bool v) {
    uint32_t s = (uint32_t)__cvta_generic_to_shared(sm);
    int sz = v ? 16 : 0;
    asm volatile("cp.async.cg.shared.global [%0], [%1], 16, %2;" :: "r"(s), "l"(g), "r"(sz));
}

// ---------------- adaLN ---------------------------------------------------------
__global__ void ada_kernel(const float* __restrict__ c,
                           const float* __restrict__ Wa, const float* __restrict__ ba,
                           const float* __restrict__ Wc, const float* __restrict__ bc,
                           float* __restrict__ outA, float* __restrict__ outC) {
    __shared__ float scs[BB * DD];
    int tid = threadIdx.x;
    for (int idx = tid; idx < BB * DD; idx += 256) {
        float v = c[idx];
        scs[idx] = v / (1.0f + __expf(-v));
    }
    __syncthreads();
    const float* W = blockIdx.y ? Wc : Wa;
    const float* bias = blockIdx.y ? bc : ba;
    float* out = blockIdx.y ? outC : outA;
    int col = blockIdx.x * 256 + tid;
    float a0 = 0.f, a1 = 0.f, a2 = 0.f, a3 = 0.f;
    for (int k = 0; k < DD; k++) {
        float w = __ldg(&W[(size_t)k * 6144 + col]);
        a0 += scs[k] * w;
        a1 += scs[DD + k] * w;
        a2 += scs[2 * DD + k] * w;
        a3 += scs[3 * DD + k] * w;
    }
    float bv = bias[col];
    out[col] = a0 + bv;
    out[6144 + col] = a1 + bv;
    out[2 * 6144 + col] = a2 + bv;
    out[3 * 6144 + col] = a3 + bv;
}

// ---------------- LayerNorm + modulate ------------------------------------------
__global__ void ln_mod_kernel(const float* __restrict__ xs, const float* __restrict__ cs,
                              const float* __restrict__ adaA, const float* __restrict__ adaC,
                              int sofs, float* __restrict__ out) {
    int r = blockIdx.x;
    int tid = threadIdx.x;
    const float* src;
    const float* ada;
    int b;
    if (r < XROWS) { b = r >> 10; src = xs + (size_t)r * DD; ada = adaA; }
    else { int rc = r - XROWS; b = rc / NC; src = cs + (size_t)rc * DD; ada = adaC; }

    float4 v = *(const float4*)(src + tid * 4);
    float s = v.x + v.y + v.z + v.w;
    float sq = v.x * v.x + v.y * v.y + v.z * v.z + v.w * v.w;
    #pragma unroll
    for (int o = 16; o; o >>= 1) {
        s += __shfl_xor_sync(0xffffffffu, s, o);
        sq += __shfl_xor_sync(0xffffffffu, sq, o);
    }
    __shared__ float rs[8], rq[8];
    __shared__ float smu, srstd;
    int w = tid >> 5;
    if ((tid & 31) == 0) { rs[w] = s; rq[w] = sq; }
    __syncthreads();
    if (tid == 0) {
        float ts = 0.f, tq = 0.f;
        #pragma unroll
        for (int i = 0; i < 8; i++) { ts += rs[i]; tq += rq[i]; }
        float mu = ts * (1.0f / DD);
        float var = tq * (1.0f / DD) - mu * mu;
        smu = mu;
        srstd = rsqrtf(var + 1e-6f);
    }
    __syncthreads();
    float mu = smu, rstd = srstd;
    const float* ap = ada + (size_t)b * 6144 + sofs;
    int col = tid * 4;
    float4 sh = *(const float4*)(ap + col);
    float4 sc = *(const float4*)(ap + 1024 + col);
    float4 o;
    o.x = (v.x - mu) * rstd * (1.0f + sc.x) + sh.x;
    o.y = (v.y - mu) * rstd * (1.0f + sc.y) + sh.y;
    o.z = (v.z - mu) * rstd * (1.0f + sc.z) + sh.z;
    o.w = (v.w - mu) * rstd * (1.0f + sc.w) + sh.w;
    *(float4*)(out + (size_t)r * DD + col) = o;
}

// ---------------- TF32 tensor-core GEMM: C = epi(A @ B + bias) -------------------
// 128x128 tile, BK=16, 256 threads, cp.async double-buffered.
// Warp grid 2x4: each warp 64x32 via m16n8k8 (4 m-tiles x 4 n-tiles).
// mode 0: none, 1: GELU, 2: C = res + gate * (acc+bias)
__global__ __launch_bounds__(256, 2) void gemm_tf32_kernel(
    const float* __restrict__ A, const float* __restrict__ B, const float* __restrict__ bias,
    float* __restrict__ C, int M, int N, int K,
    const float* __restrict__ res, const float* __restrict__ gate, int gofs, int rpb, int mode) {
    __shared__ float As[2][128][20];   // [m][k], stride 20 -> conflict-free frag loads
    __shared__ float Bs[2][16][136];   // [k][n], stride 136 -> conflict-free frag loads

    const int tid = threadIdx.x;
    const int lane = tid & 31, wid = tid >> 5;
    const int g = lane >> 2, tg = lane & 3;
    const int mbase = (wid >> 2) * 64, nbase = (wid & 3) * 32;
    const int row0 = blockIdx.y * 128, col0 = blockIdx.x * 128;

    // load indices
    const int a_row = tid >> 2;            // + 64*i
    const int a_kq = (tid & 3) * 4;
    const int b_kr = tid >> 5;             // + 8*i
    const int b_nq = (tid & 31) * 4;

    float acc[4][4][4];
    #pragma unroll
    for (int mt = 0; mt < 4; mt++)
        #pragma unroll
        for (int nt = 0; nt < 4; nt++)
            #pragma unroll
            for (int i = 0; i < 4; i++) acc[mt][nt][i] = 0.f;

    const int ntiles = K >> 4;

    auto load_stage = [&](int t, int s) {
        #pragma unroll
        for (int i = 0; i < 2; i++) {
            int row = i * 64 + a_row;
            bool v = (row0 + row) < M;
            int rr = v ? (row0 + row) : 0;
            cp16(&As[s][row][a_kq], A + (size_t)rr * K + t * 16 + a_kq, v);
        }
        #pragma unroll
        for (int i = 0; i < 2; i++) {
            int kr = i * 8 + b_kr;
            cp16(&Bs[s][kr][b_nq], B + (size_t)(t * 16 + kr) * N + col0 + b_nq, true);
        }
        asm volatile("cp.async.commit_group;");
    };

    load_stage(0, 0);

    for (int t = 0; t < ntiles; t++) {
        if (t + 1 < ntiles) {
            load_stage(t + 1, (t + 1) & 1);
            asm volatile("cp.async.wait_group 1;");
        } else {
            asm volatile("cp.async.wait_group 0;");
        }
        __syncthreads();
        const int s = t & 1;
        #pragma unroll
        for (int ks = 0; ks < 16; ks += 8) {
            uint32_t bf[4][2];
            #pragma unroll
            for (int nt = 0; nt < 4; nt++) {
                bf[nt][0] = f2tf(Bs[s][ks + tg][nbase + nt * 8 + g]);
                bf[nt][1] = f2tf(Bs[s][ks + tg + 4][nbase + nt * 8 + g]);
            }
            #pragma unroll
            for (int mt = 0; mt < 4; mt++) {
                const int mr = mbase + mt * 16 + g;
                uint32_t a0 = f2tf(As[s][mr][ks + tg]);
                uint32_t a1 = f2tf(As[s][mr + 8][ks + tg]);
                uint32_t a2 = f2tf(As[s][mr][ks + tg + 4]);
                uint32_t a3 = f2tf(As[s][mr + 8][ks + tg + 4]);
                #pragma unroll
                for (int nt = 0; nt < 4; nt++)
                    mma_tf32(acc[mt][nt][0], acc[mt][nt][1], acc[mt][nt][2], acc[mt][nt][3],
                             a0, a1, a2, a3, bf[nt][0], bf[nt][1]);
            }
        }
        __syncthreads();
    }

    // epilogue
    #pragma unroll
    for (int mt = 0; mt < 4; mt++) {
        int rA = row0 + mbase + mt * 16 + g;
        int rB = rA + 8;
        #pragma unroll
        for (int nt = 0; nt < 4; nt++) {
            int col = col0 + nbase + nt * 8 + tg * 2;
            float2 bv = *(const float2*)&bias[col];
            float v0 = acc[mt][nt][0] + bv.x;
            float v1 = acc[mt][nt][1] + bv.y;
            float v2 = acc[mt][nt][2] + bv.x;
            float v3 = acc[mt][nt][3] + bv.y;
            if (mode == 1) {
                v0 = gelu_tanh(v0); v1 = gelu_tanh(v1);
                v2 = gelu_tanh(v2); v3 = gelu_tanh(v3);
            }
            if (rA < M) {
                if (mode == 2) {
                    int bb = rA / rpb;
                    float2 gg = *(const float2*)&gate[(size_t)bb * 6144 + gofs + col];
                    float2 rr = *(const float2*)&res[(size_t)rA * N + col];
                    v0 = rr.x + gg.x * v0;
                    v1 = rr.y + gg.y * v1;
                }
                *(float2*)&C[(size_t)rA * N + col] = make_float2(v0, v1);
            }
            if (rB < M) {
                if (mode == 2) {
                    int bb = rB / rpb;
                    float2 gg = *(const float2*)&gate[(size_t)bb * 6144 + gofs + col];
                    float2 rr = *(const float2*)&res[(size_t)rB * N + col];
                    v2 = rr.x + gg.x * v2;
                    v3 = rr.y + gg.y * v3;
                }
                *(float2*)&C[(size_t)rB * N + col] = make_float2(v2, v3);
            }
        }
    }
}

// ---------------- joint flash attention (fp32 SIMT, unchanged) -------------------
__global__ __launch_bounds__(256) void attn_kernel(const float* __restrict__ qkvx,
                                                   const float* __restrict__ qkvc,
                                                   float* __restrict__ out) {
    __shared__ float Qs[64 * 64];
    __shared__ float KP[64 * 64];
    __shared__ float Vs[64 * 64];
    const int qt = blockIdx.x, h = blockIdx.y, b = blockIdx.z;
    const int tid = threadIdx.x;
    const int ty = tid >> 4, tx = tid & 15;
    const int q0 = qt * 64;

    #pragma unroll
    for (int rep = 0; rep < 4; rep++) {
        int lin = rep * 256 + tid;
        int qr = lin >> 4;
        int d4 = (lin & 15) * 4;
        int qi = q0 + qr;
        float4 v = make_float4(0.f, 0.f, 0.f, 0.f);
        if (qi < S_TOT) {
            const float* rp = (qi < NN) ? (qkvx + (size_t)(b * NN + qi) * 3072)
                                        : (qkvc + (size_t)(b * NC + (qi - NN)) * 3072);
            v = *(const float4*)(rp + h * HD + d4);
        }
        v.x *= 0.125f; v.y *= 0.125f; v.z *= 0.125f; v.w *= 0.125f;
        *(float4*)&Qs[qr * 64 + d4] = v;
    }

    float o[4][4];
    float m[4], l[4];
    #pragma unroll
    for (int i = 0; i < 4; i++) {
        m[i] = -1e30f; l[i] = 0.f;
        #pragma unroll
        for (int j = 0; j < 4; j++) o[i][j] = 0.f;
    }

    const int nkt = (S_TOT + 63) / 64;
    for (int kt = 0; kt < nkt; kt++) {
        __syncthreads();
        #pragma unroll
        for (int rep = 0; rep < 4; rep++) {
            int lin = rep * 256 + tid;
            int kr = lin >> 4;
            int d4 = (lin & 15) * 4;
            int ki = kt * 64 + kr;
            float4 kv = make_float4(0.f, 0.f, 0.f, 0.f);
            float4 vv = make_float4(0.f, 0.f, 0.f, 0.f);
            if (ki < S_TOT) {
                const float* rp = (ki < NN) ? (qkvx + (size_t)(b * NN + ki) * 3072)
                                            : (qkvc + (size_t)(b * NC + (ki - NN)) * 3072);
                kv = *(const float4*)(rp + 1024 + h * HD + d4);
                vv = *(const float4*)(rp + 2048 + h * HD + d4);
            }
            KP[(d4 + 0) * 64 + kr] = kv.x;
            KP[(d4 + 1) * 64 + kr] = kv.y;
            KP[(d4 + 2) * 64 + kr] = kv.z;
            KP[(d4 + 3) * 64 + kr] = kv.w;
            *(float4*)&Vs[kr * 64 + d4] = vv;
        }
        __syncthreads();

        float s[4][4];
        #pragma unroll
        for (int i = 0; i < 4; i++)
            #pragma unroll
            for (int j = 0; j < 4; j++) s[i][j] = 0.f;
        #pragma unroll
        for (int d4 = 0; d4 < 64; d4 += 4) {
            float4 qv[4];
            #pragma unroll
            for (int i = 0; i < 4; i++) qv[i] = *(const float4*)&Qs[(ty * 4 + i) * 64 + d4];
            #pragma unroll
            for (int dd = 0; dd < 4; dd++) {
                float4 kv4 = *(const float4*)&KP[(d4 + dd) * 64 + tx * 4];
                #pragma unroll
                for (int i = 0; i < 4; i++) {
                    float qd = ((const float*)&qv[i])[dd];
                    s[i][0] += qd * kv4.x;
                    s[i][1] += qd * kv4.y;
                    s[i][2] += qd * kv4.z;
                    s[i][3] += qd * kv4.w;
                }
            }
        }
        #pragma unroll
        for (int j = 0; j < 4; j++) {
            if (kt * 64 + tx * 4 + j >= S_TOT) {
                #pragma unroll
                for (int i = 0; i < 4; i++) s[i][j] = -1e30f;
            }
        }
        #pragma unroll
        for (int i = 0; i < 4; i++) {
            float tm = fmaxf(fmaxf(s[i][0], s[i][1]), fmaxf(s[i][2], s[i][3]));
            #pragma unroll
            for (int off = 1; off < 16; off <<= 1)
                tm = fmaxf(tm, __shfl_xor_sync(0xffffffffu, tm, off));
            float mn = fmaxf(m[i], tm);
            float sc = __expf(m[i] - mn);
            float tl = 0.f;
            #pragma unroll
            for (int j = 0; j < 4; j++) {
                float p = __expf(s[i][j] - mn);
                s[i][j] = p;
                tl += p;
            }
            #pragma unroll
            for (int off = 1; off < 16; off <<= 1)
                tl += __shfl_xor_sync(0xffffffffu, tl, off);
            l[i] = l[i] * sc + tl;
            m[i] = mn;
            #pragma unroll
            for (int j = 0; j < 4; j++) o[i][j] *= sc;
        }
        __syncthreads();
        #pragma unroll
        for (int i = 0; i < 4; i++)
            *(float4*)&KP[(ty * 4 + i) * 64 + tx * 4] =
                make_float4(s[i][0], s[i][1], s[i][2], s[i][3]);
        __syncthreads();
        #pragma unroll
        for (int k4 = 0; k4 < 64; k4 += 4) {
            float4 pv[4];
            #pragma unroll
            for (int i = 0; i < 4; i++) pv[i] = *(const float4*)&KP[(ty * 4 + i) * 64 + k4];
            #pragma unroll
            for (int kk = 0; kk < 4; kk++) {
                float4 vv = *(const float4*)&Vs[(k4 + kk) * 64 + tx * 4];
                #pragma unroll
                for (int i = 0; i < 4; i++) {
                    float p = ((const float*)&pv[i])[kk];
                    o[i][0] += p * vv.x;
                    o[i][1] += p * vv.y;
                    o[i][2] += p * vv.z;
                    o[i][3] += p * vv.w;
                }
            }
        }
    }

    #pragma unroll
    for (int i = 0; i < 4; i++) {
        int qi = q0 + ty * 4 + i;
        if (qi >= S_TOT) continue;
        int rowg = (qi < NN) ? (b * NN + qi) : (XROWS + b * NC + (qi - NN));
        float inv = 1.0f / l[i];
        float4 ov = make_float4(o[i][0] * inv, o[i][1] * inv, o[i][2] * inv, o[i][3] * inv);
        *(float4*)&out[(size_t)rowg * DD + h * HD + tx * 4] = ov;
    }
}

// ---------------- launcher ----------------
extern "C" void kernel_launch(void* const* d_in, const int* in_sizes, int n_in,
                              void* d_out, int out_size) {
    const float* x       = (const float*)d_in[0];
    const float* cond    = (const float*)d_in[1];
    const float* c       = (const float*)d_in[2];
    const float* W_ada   = (const float*)d_in[3];
    const float* b_ada   = (const float*)d_in[4];
    const float* W_ada_c = (const float*)d_in[5];
    const float* b_ada_c = (const float*)d_in[6];
    const float* W_qkv   = (const float*)d_in[7];
    const float* b_qkv   = (const float*)d_in[8];
    const float* W_proj  = (const float*)d_in[9];
    const float* b_proj  = (const float*)d_in[10];
    const float* W_qkv_c = (const float*)d_in[11];
    const float* b_qkv_c = (const float*)d_in[12];
    const float* W_proj_c= (const float*)d_in[13];
    const float* b_proj_c= (const float*)d_in[14];
    const float* W_fc1   = (const float*)d_in[15];
    const float* b_fc1   = (const float*)d_in[16];
    const float* W_fc2   = (const float*)d_in[17];
    const float* b_fc2   = (const float*)d_in[18];
    const float* W_fc1_c = (const float*)d_in[19];
    const float* b_fc1_c = (const float*)d_in[20];
    const float* W_fc2_c = (const float*)d_in[21];
    const float* b_fc2_c = (const float*)d_in[22];
    float* out = (float*)d_out;

    float *adaA, *adaC, *xt, *qkvx, *qkvc, *attn, *xmid, *cmid, *hx, *hc;
    cudaGetSymbolAddress((void**)&adaA, g_adaA);
    cudaGetSymbolAddress((void**)&adaC, g_adaC);
    cudaGetSymbolAddress((void**)&xt,   g_xt);
    cudaGetSymbolAddress((void**)&qkvx, g_qkvx);
    cudaGetSymbolAddress((void**)&qkvc, g_qkvc);
    cudaGetSymbolAddress((void**)&attn, g_attn);
    cudaGetSymbolAddress((void**)&xmid, g_xmid);
    cudaGetSymbolAddress((void**)&cmid, g_cmid);
    cudaGetSymbolAddress((void**)&hx,   g_hx);
    cudaGetSymbolAddress((void**)&hc,   g_hc);

    // 1. adaLN
    ada_kernel<<<dim3(6144 / 256, 2), 256>>>(c, W_ada, b_ada, W_ada_c, b_ada_c, adaA, adaC);
    // 2. LN + modulate (MSA)
    ln_mod_kernel<<<TROWS, 256>>>(x, cond, adaA, adaC, 0, xt);
    // 3. QKV GEMMs
    gemm_tf32_kernel<<<dim3(3072 / 128, XROWS / 128), 256>>>(xt, W_qkv, b_qkv, qkvx,
        XROWS, 3072, 1024, nullptr, nullptr, 0, 1, 0);
    gemm_tf32_kernel<<<dim3(3072 / 128, (CROWS + 127) / 128), 256>>>(xt + (size_t)XROWS * DD,
        W_qkv_c, b_qkv_c, qkvc, CROWS, 3072, 1024, nullptr, nullptr, 0, 1, 0);
    // 4. joint attention
    attn_kernel<<<dim3((S_TOT + 63) / 64, HH, BB), 256>>>(qkvx, qkvc, attn);
    // 5. proj + gated residual
    gemm_tf32_kernel<<<dim3(1024 / 128, XROWS / 128), 256>>>(attn, W_proj, b_proj, xmid,
        XROWS, 1024, 1024, x, adaA, 2048, NN, 2);
    gemm_tf32_kernel<<<dim3(1024 / 128, (CROWS + 127) / 128), 256>>>(attn + (size_t)XROWS * DD,
        W_proj_c, b_proj_c, cmid, CROWS, 1024, 1024, cond, adaC, 2048, NC, 2);
    // 6. LN + modulate (MLP)
    ln_mod_kernel<<<TROWS, 256>>>(xmid, cmid, adaA, adaC, 3072, xt);
    // 7. fc1 + GELU
    gemm_tf32_kernel<<<dim3(DFF / 128, XROWS / 128), 256>>>(xt, W_fc1, b_fc1, hx,
        XROWS, DFF, 1024, nullptr, nullptr, 0, 1, 1);
    gemm_tf32_kernel<<<dim3(DFF / 128, (CROWS + 127) / 128), 256>>>(xt + (size_t)XROWS * DD,
        W_fc1_c, b_fc1_c, hc, CROWS, DFF, 1024, nullptr, nullptr, 0, 1, 1);
    // 8. fc2 + gated residual -> d_out
    gemm_tf32_kernel<<<dim3(1024 / 128, XROWS / 128), 256>>>(hx, W_fc2, b_fc2, out,
        XROWS, 1024, DFF, xmid, adaA, 5120, NN, 2);
    gemm_tf32_kernel<<<dim3(1024 / 128, (CROWS + 127) / 128), 256>>>(hc, W_fc2_c, b_fc2_c,
        out + (size_t)XROWS * DD, CROWS, 1024, DFF, cmid, adaC, 5120, NC, 2);
}

// round 3
// speedup vs baseline: 4.0712x; 1.7681x over previous
#include <cuda_runtime.h>
#include <cuda_bf16.h>
#include <math.h>
#include <stdint.h>

// Shapes (fixed per reference)
#define BB 4
#define NN 1024
#define NC 77
#define DD 1024
#define HH 16
#define HD 64
#define DFF 4096
#define S_TOT (NN + NC)        // 1101
#define XROWS (BB * NN)        // 4096
#define CROWS (BB * NC)        // 308
#define TROWS (XROWS + CROWS)  // 4404

// ---------------- scratch ----------------
__device__ float g_adaA[BB * 6 * DD];
__device__ float g_adaC[BB * 6 * DD];
__device__ float g_xt[TROWS * DD];
__device__ float g_qkvx[XROWS * 3 * DD];
__device__ float g_qkvc[CROWS * 3 * DD];
__device__ float g_attn[TROWS * DD];
__device__ float g_xmid[XROWS * DD];
__device__ float g_cmid[CROWS * DD];
__device__ float g_hx[XROWS * DFF];
__device__ float g_hc[CROWS * DFF];

// ---------------- helpers ----------------
__device__ __forceinline__ float gelu_tanh(float x) {
    float x3 = x * x * x;
    float t = tanhf(0.7978845608028654f * (x + 0.044715f * x3));
    return 0.5f * x * (1.0f + t);
}

__device__ __forceinline__ uint32_t f2tf(float f) {
    uint32_t r;
    asm("cvt.rna.tf32.f32 %0, %1;" : "=r"(r) : "f"(f));
    return r;
}
__device__ __forceinline__ float tfround(float f) { return __uint_as_float(f2tf(f)); }

__device__ __forceinline__ void mma_tf32(float& c0, float& c1, float& c2, float& c3,
                                         uint32_t a0, uint32_t a1, uint32_t a2, uint32_t a3,
                                         uint32_t b0, uint32_t b1) {
    asm volatile("mma.sync.aligned.m16n8k8.row.col.f32.tf32.tf32.f32 "
                 "{%0,%1,%2,%3}, {%4,%5,%6,%7}, {%8,%9}, {%0,%1,%2,%3};"
                 : "+f"(c0), "+f"(c1), "+f"(c2), "+f"(c3)
                 : "r"(a0), "r"(a1), "r"(a2), "r"(a3), "r"(b0), "r"(b1));
}

__device__ __forceinline__ void mma_bf16(float& c0, float& c1, float& c2, float& c3,
                                         uint32_t a0, uint32_t a1, uint32_t a2, uint32_t a3,
                                         uint32_t b0, uint32_t b1) {
    asm volatile("mma.sync.aligned.m16n8k16.row.col.f32.bf16.bf16.f32 "
                 "{%0,%1,%2,%3}, {%4,%5,%6,%7}, {%8,%9}, {%0,%1,%2,%3};"
                 : "+f"(c0), "+f"(c1), "+f"(c2), "+f"(c3)
                 : "r"(a0), "r"(a1), "r"(a2), "r"(a3), "r"(b0), "r"(b1));
}

// pack two floats to bf16x2: low 16 bits = lo, high = hi
__device__ __forceinline__ uint32_t pk_bf16(float lo, float hi) {
    uint32_t r;
    asm("cvt.rn.bf16x2.f32 %0, %1, %2;" : "=r"(r) : "f"(hi), "f"(lo));
    return r;
}

__device__ __forceinline__ void cp16(void* sm, const void* g, bool v) {
    uint32_t s = (uint32_t)__cvta_generic_to_shared(sm);
    int sz = v ? 16 : 0;
    asm volatile("cp.async.cg.shared.global [%0], [%1], 16, %2;" :: "r"(s), "l"(g), "r"(sz));
}

// ---------------- adaLN ---------------------------------------------------------
__global__ void ada_kernel(const float* __restrict__ c,
                           const float* __restrict__ Wa, const float* __restrict__ ba,
                           const float* __restrict__ Wc, const float* __restrict__ bc,
                           float* __restrict__ outA, float* __restrict__ outC) {
    __shared__ float scs[BB * DD];
    int tid = threadIdx.x;
    for (int idx = tid; idx < BB * DD; idx += 256) {
        float v = c[idx];
        scs[idx] = v / (1.0f + __expf(-v));
    }
    __syncthreads();
    const float* W = blockIdx.y ? Wc : Wa;
    const float* bias = blockIdx.y ? bc : ba;
    float* out = blockIdx.y ? outC : outA;
    int col = blockIdx.x * 256 + tid;
    float a0 = 0.f, a1 = 0.f, a2 = 0.f, a3 = 0.f;
    for (int k = 0; k < DD; k++) {
        float w = __ldg(&W[(size_t)k * 6144 + col]);
        a0 += scs[k] * w;
        a1 += scs[DD + k] * w;
        a2 += scs[2 * DD + k] * w;
        a3 += scs[3 * DD + k] * w;
    }
    float bv = bias[col];
    out[col] = a0 + bv;
    out[6144 + col] = a1 + bv;
    out[2 * 6144 + col] = a2 + bv;
    out[3 * 6144 + col] = a3 + bv;
}

// ---------------- LayerNorm + modulate (writes tf32-rounded) ---------------------
__global__ void ln_mod_kernel(const float* __restrict__ xs, const float* __restrict__ cs,
                              const float* __restrict__ adaA, const float* __restrict__ adaC,
                              int sofs, float* __restrict__ out) {
    int r = blockIdx.x;
    int tid = threadIdx.x;
    const float* src;
    const float* ada;
    int b;
    if (r < XROWS) { b = r >> 10; src = xs + (size_t)r * DD; ada = adaA; }
    else { int rc = r - XROWS; b = rc / NC; src = cs + (size_t)rc * DD; ada = adaC; }

    float4 v = *(const float4*)(src + tid * 4);
    float s = v.x + v.y + v.z + v.w;
    float sq = v.x * v.x + v.y * v.y + v.z * v.z + v.w * v.w;
    #pragma unroll
    for (int o = 16; o; o >>= 1) {
        s += __shfl_xor_sync(0xffffffffu, s, o);
        sq += __shfl_xor_sync(0xffffffffu, sq, o);
    }
    __shared__ float rs[8], rq[8];
    __shared__ float smu, srstd;
    int w = tid >> 5;
    if ((tid & 31) == 0) { rs[w] = s; rq[w] = sq; }
    __syncthreads();
    if (tid == 0) {
        float ts = 0.f, tq = 0.f;
        #pragma unroll
        for (int i = 0; i < 8; i++) { ts += rs[i]; tq += rq[i]; }
        float mu = ts * (1.0f / DD);
        float var = tq * (1.0f / DD) - mu * mu;
        smu = mu;
        srstd = rsqrtf(var + 1e-6f);
    }
    __syncthreads();
    float mu = smu, rstd = srstd;
    const float* ap = ada + (size_t)b * 6144 + sofs;
    int col = tid * 4;
    float4 sh = *(const float4*)(ap + col);
    float4 sc = *(const float4*)(ap + 1024 + col);
    float4 o;
    o.x = tfround((v.x - mu) * rstd * (1.0f + sc.x) + sh.x);
    o.y = tfround((v.y - mu) * rstd * (1.0f + sc.y) + sh.y);
    o.z = tfround((v.z - mu) * rstd * (1.0f + sc.z) + sh.z);
    o.w = tfround((v.w - mu) * rstd * (1.0f + sc.w) + sh.w);
    *(float4*)(out + (size_t)r * DD + col) = o;
}

// ---------------- fused TF32 GEMM pair: two problems sharing N,K -----------------
// blockIdx.y < ny1 -> problem 1 (rows of A1/C1); else problem 2.
// mode 0: round->C, 1: GELU->round->C, 2: C = res + gate*(acc+bias) (no rounding)
__global__ __launch_bounds__(256, 2) void gemm_tf32_fused(
    const float* __restrict__ A1, const float* __restrict__ B1, const float* __restrict__ bias1,
    float* __restrict__ C1, int M1,
    const float* __restrict__ A2, const float* __restrict__ B2, const float* __restrict__ bias2,
    float* __restrict__ C2, int M2,
    int N, int K, int ny1,
    const float* __restrict__ res1, const float* __restrict__ gate1, int rpb1,
    const float* __restrict__ res2, const float* __restrict__ gate2, int rpb2,
    int gofs, int mode) {
    __shared__ float As[2][128][20];
    __shared__ float Bs[2][16][136];

    const int tid = threadIdx.x;
    const int lane = tid & 31, wid = tid >> 5;
    const int g = lane >> 2, tg = lane & 3;
    const int mbase = (wid >> 2) * 64, nbase = (wid & 3) * 32;

    const float *A, *B, *bias, *res, *gate;
    float* C;
    int M, rpb, row0;
    if ((int)blockIdx.y < ny1) {
        A = A1; B = B1; bias = bias1; C = C1; M = M1; res = res1; gate = gate1; rpb = rpb1;
        row0 = blockIdx.y * 128;
    } else {
        A = A2; B = B2; bias = bias2; C = C2; M = M2; res = res2; gate = gate2; rpb = rpb2;
        row0 = (blockIdx.y - ny1) * 128;
    }
    const int col0 = blockIdx.x * 128;

    const int a_row = tid >> 2;
    const int a_kq = (tid & 3) * 4;
    const int b_kr = tid >> 5;
    const int b_nq = (tid & 31) * 4;

    float acc[4][4][4];
    #pragma unroll
    for (int mt = 0; mt < 4; mt++)
        #pragma unroll
        for (int nt = 0; nt < 4; nt++)
            #pragma unroll
            for (int i = 0; i < 4; i++) acc[mt][nt][i] = 0.f;

    const int ntiles = K >> 4;

    auto load_stage = [&](int t, int s) {
        #pragma unroll
        for (int i = 0; i < 2; i++) {
            int row = i * 64 + a_row;
            bool v = (row0 + row) < M;
            int rr = v ? (row0 + row) : 0;
            cp16(&As[s][row][a_kq], A + (size_t)rr * K + t * 16 + a_kq, v);
        }
        #pragma unroll
        for (int i = 0; i < 2; i++) {
            int kr = i * 8 + b_kr;
            cp16(&Bs[s][kr][b_nq], B + (size_t)(t * 16 + kr) * N + col0 + b_nq, true);
        }
        asm volatile("cp.async.commit_group;");
    };

    load_stage(0, 0);

    for (int t = 0; t < ntiles; t++) {
        if (t + 1 < ntiles) {
            load_stage(t + 1, (t + 1) & 1);
            asm volatile("cp.async.wait_group 1;");
        } else {
            asm volatile("cp.async.wait_group 0;");
        }
        __syncthreads();
        const int s = t & 1;
        #pragma unroll
        for (int ks = 0; ks < 16; ks += 8) {
            uint32_t bf[4][2];
            #pragma unroll
            for (int nt = 0; nt < 4; nt++) {
                bf[nt][0] = __float_as_uint(Bs[s][ks + tg][nbase + nt * 8 + g]);
                bf[nt][1] = __float_as_uint(Bs[s][ks + tg + 4][nbase + nt * 8 + g]);
            }
            #pragma unroll
            for (int mt = 0; mt < 4; mt++) {
                const int mr = mbase + mt * 16 + g;
                uint32_t a0 = __float_as_uint(As[s][mr][ks + tg]);
                uint32_t a1 = __float_as_uint(As[s][mr + 8][ks + tg]);
                uint32_t a2 = __float_as_uint(As[s][mr][ks + tg + 4]);
                uint32_t a3 = __float_as_uint(As[s][mr + 8][ks + tg + 4]);
                #pragma unroll
                for (int nt = 0; nt < 4; nt++)
                    mma_tf32(acc[mt][nt][0], acc[mt][nt][1], acc[mt][nt][2], acc[mt][nt][3],
                             a0, a1, a2, a3, bf[nt][0], bf[nt][1]);
            }
        }
        __syncthreads();
    }

    #pragma unroll
    for (int mt = 0; mt < 4; mt++) {
        int rA = row0 + mbase + mt * 16 + g;
        int rB = rA + 8;
        #pragma unroll
        for (int nt = 0; nt < 4; nt++) {
            int col = col0 + nbase + nt * 8 + tg * 2;
            float2 bv = *(const float2*)&bias[col];
            float v0 = acc[mt][nt][0] + bv.x;
            float v1 = acc[mt][nt][1] + bv.y;
            float v2 = acc[mt][nt][2] + bv.x;
            float v3 = acc[mt][nt][3] + bv.y;
            if (mode == 1) {
                v0 = gelu_tanh(v0); v1 = gelu_tanh(v1);
                v2 = gelu_tanh(v2); v3 = gelu_tanh(v3);
            }
            if (mode != 2) {
                v0 = tfround(v0); v1 = tfround(v1);
                v2 = tfround(v2); v3 = tfround(v3);
            }
            if (rA < M) {
                if (mode == 2) {
                    int bb = rA / rpb;
                    float2 gg = *(const float2*)&gate[(size_t)bb * 6144 + gofs + col];
                    float2 rr = *(const float2*)&res[(size_t)rA * N + col];
                    v0 = rr.x + gg.x * v0;
                    v1 = rr.y + gg.y * v1;
                }
                *(float2*)&C[(size_t)rA * N + col] = make_float2(v0, v1);
            }
            if (rB < M) {
                if (mode == 2) {
                    int bb = rB / rpb;
                    float2 gg = *(const float2*)&gate[(size_t)bb * 6144 + gofs + col];
                    float2 rr = *(const float2*)&res[(size_t)rB * N + col];
                    v2 = rr.x + gg.x * v2;
                    v3 = rr.y + gg.y * v3;
                }
                *(float2*)&C[(size_t)rB * N + col] = make_float2(v2, v3);
            }
        }
    }
}

// ---------------- tensor-core joint flash attention ------------------------------
// grid (18, H, B), block 128 (4 warps x 16 q-rows = 64 q rows per block).
// BK=32 keys per iteration, double-buffered cp.async.
// QK^T: tf32 m16n8k8 (Q frags in regs); softmax in accum layout; P@V: bf16 m16n8k16.
__global__ void attn_kernel(const float* __restrict__ qkvx,
                            const float* __restrict__ qkvc,
                            float* __restrict__ out) {
    __shared__ float Ks[2][32][68];
    __shared__ float Vs[2][32][68];

    const int qt = blockIdx.x, h = blockIdx.y, b = blockIdx.z;
    const int tid = threadIdx.x;
    const int lane = tid & 31, wid = tid >> 5;
    const int g = lane >> 2, tg = lane & 3;
    const int q0 = qt * 64;

    // ---- stage Q (scaled) into Ks area [64][68], extract tf32 frags ----
    {
        float* qs = &Ks[0][0][0];
        #pragma unroll
        for (int i = 0; i < 8; i++) {
            int idx = i * 128 + tid;
            int row = idx >> 4, c4 = (idx & 15) * 4;
            int qi = q0 + row;
            float4 v = make_float4(0.f, 0.f, 0.f, 0.f);
            if (qi < S_TOT) {
                const float* rp = (qi < NN) ? (qkvx + (size_t)(b * NN + qi) * 3072)
                                            : (qkvc + (size_t)(b * NC + (qi - NN)) * 3072);
                v = *(const float4*)(rp + h * HD + c4);
            }
            v.x *= 0.125f; v.y *= 0.125f; v.z *= 0.125f; v.w *= 0.125f;
            *(float4*)(qs + row * 68 + c4) = v;
        }
    }
    __syncthreads();
    uint32_t qf[8][4];
    {
        const float* qs = &Ks[0][0][0];
        int r0 = wid * 16 + g;
        #pragma unroll
        for (int ks = 0; ks < 8; ks++) {
            qf[ks][0] = f2tf(qs[r0 * 68 + ks * 8 + tg]);
            qf[ks][1] = f2tf(qs[(r0 + 8) * 68 + ks * 8 + tg]);
            qf[ks][2] = f2tf(qs[r0 * 68 + ks * 8 + tg + 4]);
            qf[ks][3] = f2tf(qs[(r0 + 8) * 68 + ks * 8 + tg + 4]);
        }
    }
    __syncthreads();

    float o[8][4];
    #pragma unroll
    for (int nt = 0; nt < 8; nt++)
        #pragma unroll
        for (int i = 0; i < 4; i++) o[nt][i] = 0.f;
    float m0 = -1e30f, m1 = -1e30f, l0 = 0.f, l1 = 0.f;

    const int nkt = (S_TOT + 31) / 32;  // 35

    auto load_kv = [&](int kt, int st) {
        #pragma unroll
        for (int i = 0; i < 4; i++) {
            int idx = i * 128 + tid;
            int r = idx >> 4, c4 = (idx & 15) * 4;
            int key = kt * 32 + r;
            bool v = key < S_TOT;
            const float* rp = qkvx;
            if (v) rp = (key < NN) ? (qkvx + (size_t)(b * NN + key) * 3072)
                                   : (qkvc + (size_t)(b * NC + (key - NN)) * 3072);
            cp16(&Ks[st][r][c4], rp + 1024 + h * HD + c4, v);
            cp16(&Vs[st][r][c4], rp + 2048 + h * HD + c4, v);
        }
        asm volatile("cp.async.commit_group;");
    };

    load_kv(0, 0);

    for (int kt = 0; kt < nkt; kt++) {
        if (kt + 1 < nkt) {
            load_kv(kt + 1, (kt + 1) & 1);
            asm volatile("cp.async.wait_group 1;");
        } else {
            asm volatile("cp.async.wait_group 0;");
        }
        __syncthreads();
        const int s = kt & 1;

        // S = Q @ K^T : 4 n-tiles (32 keys), 8 k-slices
        float sa[4][4];
        #pragma unroll
        for (int nt = 0; nt < 4; nt++)
            #pragma unroll
            for (int i = 0; i < 4; i++) sa[nt][i] = 0.f;
        #pragma unroll
        for (int ks = 0; ks < 8; ks++) {
            #pragma unroll
            for (int nt = 0; nt < 4; nt++) {
                uint32_t b0 = __float_as_uint(Ks[s][nt * 8 + g][ks * 8 + tg]);
                uint32_t b1 = __float_as_uint(Ks[s][nt * 8 + g][ks * 8 + tg + 4]);
                mma_tf32(sa[nt][0], sa[nt][1], sa[nt][2], sa[nt][3],
                         qf[ks][0], qf[ks][1], qf[ks][2], qf[ks][3], b0, b1);
            }
        }

        // mask OOB keys
        #pragma unroll
        for (int nt = 0; nt < 4; nt++) {
            int k0 = kt * 32 + nt * 8 + 2 * tg;
            if (k0 >= S_TOT) { sa[nt][0] = -1e30f; sa[nt][2] = -1e30f; }
            if (k0 + 1 >= S_TOT) { sa[nt][1] = -1e30f; sa[nt][3] = -1e30f; }
        }

        // online softmax (rows g and g+8; quad-shfl reduce over tg)
        float mx0 = -1e30f, mx1 = -1e30f;
        #pragma unroll
        for (int nt = 0; nt < 4; nt++) {
            mx0 = fmaxf(mx0, fmaxf(sa[nt][0], sa[nt][1]));
            mx1 = fmaxf(mx1, fmaxf(sa[nt][2], sa[nt][3]));
        }
        mx0 = fmaxf(mx0, __shfl_xor_sync(0xffffffffu, mx0, 1));
        mx0 = fmaxf(mx0, __shfl_xor_sync(0xffffffffu, mx0, 2));
        mx1 = fmaxf(mx1, __shfl_xor_sync(0xffffffffu, mx1, 1));
        mx1 = fmaxf(mx1, __shfl_xor_sync(0xffffffffu, mx1, 2));
        float mn0 = fmaxf(m0, mx0), mn1 = fmaxf(m1, mx1);
        float sc0 = __expf(m0 - mn0), sc1 = __expf(m1 - mn1);
        float sum0 = 0.f, sum1 = 0.f;
        #pragma unroll
        for (int nt = 0; nt < 4; nt++) {
            sa[nt][0] = __expf(sa[nt][0] - mn0);
            sa[nt][1] = __expf(sa[nt][1] - mn0);
            sa[nt][2] = __expf(sa[nt][2] - mn1);
            sa[nt][3] = __expf(sa[nt][3] - mn1);
            sum0 += sa[nt][0] + sa[nt][1];
            sum1 += sa[nt][2] + sa[nt][3];
        }
        sum0 += __shfl_xor_sync(0xffffffffu, sum0, 1);
        sum0 += __shfl_xor_sync(0xffffffffu, sum0, 2);
        sum1 += __shfl_xor_sync(0xffffffffu, sum1, 1);
        sum1 += __shfl_xor_sync(0xffffffffu, sum1, 2);
        l0 = l0 * sc0 + sum0;
        l1 = l1 * sc1 + sum1;
        m0 = mn0; m1 = mn1;
        #pragma unroll
        for (int nt = 0; nt < 8; nt++) {
            o[nt][0] *= sc0; o[nt][1] *= sc0;
            o[nt][2] *= sc1; o[nt][3] *= sc1;
        }

        // P -> bf16 A-frags (accum layout == A-frag layout), then O += P @ V
        uint32_t pf[2][4];
        #pragma unroll
        for (int k2 = 0; k2 < 2; k2++) {
            pf[k2][0] = pk_bf16(sa[2 * k2][0], sa[2 * k2][1]);
            pf[k2][1] = pk_bf16(sa[2 * k2][2], sa[2 * k2][3]);
            pf[k2][2] = pk_bf16(sa[2 * k2 + 1][0], sa[2 * k2 + 1][1]);
            pf[k2][3] = pk_bf16(sa[2 * k2 + 1][2], sa[2 * k2 + 1][3]);
        }
        #pragma unroll
        for (int k2 = 0; k2 < 2; k2++) {
            #pragma unroll
            for (int nt = 0; nt < 8; nt++) {
                int kr = k2 * 16 + 2 * tg;
                int dc = nt * 8 + g;
                uint32_t b0 = pk_bf16(Vs[s][kr][dc], Vs[s][kr + 1][dc]);
                uint32_t b1 = pk_bf16(Vs[s][kr + 8][dc], Vs[s][kr + 9][dc]);
                mma_bf16(o[nt][0], o[nt][1], o[nt][2], o[nt][3],
                         pf[k2][0], pf[k2][1], pf[k2][2], pf[k2][3], b0, b1);
            }
        }
        __syncthreads();
    }

    // write output (tf32-rounded; feeds proj GEMM A-side)
    float inv0 = 1.0f / l0, inv1 = 1.0f / l1;
    int r0 = q0 + wid * 16 + g;
    int r1 = r0 + 8;
    #pragma unroll
    for (int nt = 0; nt < 8; nt++) {
        int col = h * HD + nt * 8 + 2 * tg;
        if (r0 < S_TOT) {
            int rowg = (r0 < NN) ? (b * NN + r0) : (XROWS + b * NC + (r0 - NN));
            *(float2*)&out[(size_t)rowg * DD + col] =
                make_float2(tfround(o[nt][0] * inv0), tfround(o[nt][1] * inv0));
        }
        if (r1 < S_TOT) {
            int rowg = (r1 < NN) ? (b * NN + r1) : (XROWS + b * NC + (r1 - NN));
            *(float2*)&out[(size_t)rowg * DD + col] =
                make_float2(tfround(o[nt][2] * inv1), tfround(o[nt][3] * inv1));
        }
    }
}

// ---------------- launcher ----------------
extern "C" void kernel_launch(void* const* d_in, const int* in_sizes, int n_in,
                              void* d_out, int out_size) {
    const float* x       = (const float*)d_in[0];
    const float* cond    = (const float*)d_in[1];
    const float* c       = (const float*)d_in[2];
    const float* W_ada   = (const float*)d_in[3];
    const float* b_ada   = (const float*)d_in[4];
    const float* W_ada_c = (const float*)d_in[5];
    const float* b_ada_c = (const float*)d_in[6];
    const float* W_qkv   = (const float*)d_in[7];
    const float* b_qkv   = (const float*)d_in[8];
    const float* W_proj  = (const float*)d_in[9];
    const float* b_proj  = (const float*)d_in[10];
    const float* W_qkv_c = (const float*)d_in[11];
    const float* b_qkv_c = (const float*)d_in[12];
    const float* W_proj_c= (const float*)d_in[13];
    const float* b_proj_c= (const float*)d_in[14];
    const float* W_fc1   = (const float*)d_in[15];
    const float* b_fc1   = (const float*)d_in[16];
    const float* W_fc2   = (const float*)d_in[17];
    const float* b_fc2   = (const float*)d_in[18];
    const float* W_fc1_c = (const float*)d_in[19];
    const float* b_fc1_c = (const float*)d_in[20];
    const float* W_fc2_c = (const float*)d_in[21];
    const float* b_fc2_c = (const float*)d_in[22];
    float* out = (float*)d_out;

    float *adaA, *adaC, *xt, *qkvx, *qkvc, *attn, *xmid, *cmid, *hx, *hc;
    cudaGetSymbolAddress((void**)&adaA, g_adaA);
    cudaGetSymbolAddress((void**)&adaC, g_adaC);
    cudaGetSymbolAddress((void**)&xt,   g_xt);
    cudaGetSymbolAddress((void**)&qkvx, g_qkvx);
    cudaGetSymbolAddress((void**)&qkvc, g_qkvc);
    cudaGetSymbolAddress((void**)&attn, g_attn);
    cudaGetSymbolAddress((void**)&xmid, g_xmid);
    cudaGetSymbolAddress((void**)&cmid, g_cmid);
    cudaGetSymbolAddress((void**)&hx,   g_hx);
    cudaGetSymbolAddress((void**)&hc,   g_hc);

    const float* xtc = xt + (size_t)XROWS * DD;
    const float* attc = attn + (size_t)XROWS * DD;
    const int NY1 = XROWS / 128;                 // 32
    const int NY2 = (CROWS + 127) / 128;         // 3

    // 1. adaLN
    ada_kernel<<<dim3(6144 / 256, 2), 256>>>(c, W_ada, b_ada, W_ada_c, b_ada_c, adaA, adaC);
    // 2. LN + modulate (MSA)
    ln_mod_kernel<<<TROWS, 256>>>(x, cond, adaA, adaC, 0, xt);
    // 3. fused QKV GEMMs (x + c)
    gemm_tf32_fused<<<dim3(3072 / 128, NY1 + NY2), 256>>>(
        xt, W_qkv, b_qkv, qkvx, XROWS,
        xtc, W_qkv_c, b_qkv_c, qkvc, CROWS,
        3072, 1024, NY1, nullptr, nullptr, 1, nullptr, nullptr, 1, 0, 0);
    // 4. joint attention
    attn_kernel<<<dim3((S_TOT + 63) / 64, HH, BB), 128>>>(qkvx, qkvc, attn);
    // 5. fused proj + gated residual
    gemm_tf32_fused<<<dim3(1024 / 128, NY1 + NY2), 256>>>(
        attn, W_proj, b_proj, xmid, XROWS,
        attc, W_proj_c, b_proj_c, cmid, CROWS,
        1024, 1024, NY1, x, adaA, NN, cond, adaC, NC, 2048, 2);
    // 6. LN + modulate (MLP)
    ln_mod_kernel<<<TROWS, 256>>>(xmid, cmid, adaA, adaC, 3072, xt);
    // 7. fused fc1 + GELU
    gemm_tf32_fused<<<dim3(DFF / 128, NY1 + NY2), 256>>>(
        xt, W_fc1, b_fc1, hx, XROWS,
        xtc, W_fc1_c, b_fc1_c, hc, CROWS,
        DFF, 1024, NY1, nullptr, nullptr, 1, nullptr, nullptr, 1, 0, 1);
    // 8. fused fc2 + gated residual -> d_out
    gemm_tf32_fused<<<dim3(1024 / 128, NY1 + NY2), 256>>>(
        hx, W_fc2, b_fc2, out, XROWS,
        hc, W_fc2_c, b_fc2_c, out + (size_t)XROWS * DD, CROWS,
        1024, DFF, NY1, xmid, adaA, NN, cmid, adaC, NC, 5120, 2);
}

// round 6
// speedup vs baseline: 6.8087x; 1.6724x over previous
#include <cuda_runtime.h>
#include <cuda_fp16.h>
#include <math.h>
#include <stdint.h>

// Shapes (fixed per reference)
#define BB 4
#define NN 1024
#define NC 77
#define DD 1024
#define HH 16
#define HD 64
#define DFF 4096
#define S_TOT (NN + NC)        // 1101
#define XROWS (BB * NN)        // 4096
#define CROWS (BB * NC)        // 308
#define TROWS (XROWS + CROWS)  // 4404

// ---------------- scratch ----------------
__device__ float g_adaA[BB * 6 * DD];
__device__ float g_adaC[BB * 6 * DD];
__device__ float g_xmid[XROWS * DD];
__device__ float g_cmid[CROWS * DD];
// fp16 activations
__device__ __half h_xt[TROWS * DD];
__device__ __half h_qkvx[XROWS * 3 * DD];
__device__ __half h_qkvc[CROWS * 3 * DD];
__device__ __half h_attn[TROWS * DD];
__device__ __half h_hx[XROWS * DFF];
__device__ __half h_hc[CROWS * DFF];
// fp16 weights
__device__ __half h_Wqkv[DD * 3 * DD];
__device__ __half h_Wqkvc[DD * 3 * DD];
__device__ __half h_Wproj[DD * DD];
__device__ __half h_Wprojc[DD * DD];
__device__ __half h_Wfc1[DD * DFF];
__device__ __half h_Wfc1c[DD * DFF];
__device__ __half h_Wfc2[DFF * DD];
__device__ __half h_Wfc2c[DFF * DD];

// ---------------- helpers ----------------
__device__ __forceinline__ float gelu_tanh(float x) {
    float x3 = x * x * x;
    float t = tanhf(0.7978845608028654f * (x + 0.044715f * x3));
    return 0.5f * x * (1.0f + t);
}

__device__ __forceinline__ void mma_f16(float& c0, float& c1, float& c2, float& c3,
                                        uint32_t a0, uint32_t a1, uint32_t a2, uint32_t a3,
                                        uint32_t b0, uint32_t b1) {
    asm volatile("mma.sync.aligned.m16n8k16.row.col.f32.f16.f16.f32 "
                 "{%0,%1,%2,%3}, {%4,%5,%6,%7}, {%8,%9}, {%0,%1,%2,%3};"
                 : "+f"(c0), "+f"(c1), "+f"(c2), "+f"(c3)
                 : "r"(a0), "r"(a1), "r"(a2), "r"(a3), "r"(b0), "r"(b1));
}

__device__ __forceinline__ void ldsm4(uint32_t* r, uint32_t a) {
    asm volatile("ldmatrix.sync.aligned.m8n8.x4.shared.b16 {%0,%1,%2,%3}, [%4];"
                 : "=r"(r[0]), "=r"(r[1]), "=r"(r[2]), "=r"(r[3]) : "r"(a));
}
__device__ __forceinline__ void ldsm4t(uint32_t* r, uint32_t a) {
    asm volatile("ldmatrix.sync.aligned.m8n8.x4.trans.shared.b16 {%0,%1,%2,%3}, [%4];"
                 : "=r"(r[0]), "=r"(r[1]), "=r"(r[2]), "=r"(r[3]) : "r"(a));
}

__device__ __forceinline__ uint32_t pk_f16(float lo, float hi) {
    __half2 h = __floats2half2_rn(lo, hi);
    return *(uint32_t*)&h;
}

__device__ __forceinline__ void cp16(void* sm, const void* g, bool v) {
    uint32_t s = (uint32_t)__cvta_generic_to_shared(sm);
    int sz = v ? 16 : 0;
    asm volatile("cp.async.cg.shared.global [%0], [%1], 16, %2;" :: "r"(s), "l"(g), "r"(sz));
}

// ---------------- fp32 -> fp16 convert ----------------
__global__ void f2h_kernel(const float* __restrict__ in, __half* __restrict__ out, int n) {
    int i = (blockIdx.x * 256 + threadIdx.x) * 8;
    if (i + 8 <= n) {
        float4 a = *(const float4*)(in + i);
        float4 b = *(const float4*)(in + i + 4);
        __half2 h0 = __floats2half2_rn(a.x, a.y);
        __half2 h1 = __floats2half2_rn(a.z, a.w);
        __half2 h2 = __floats2half2_rn(b.x, b.y);
        __half2 h3 = __floats2half2_rn(b.z, b.w);
        uint4 pk;
        pk.x = *(uint32_t*)&h0; pk.y = *(uint32_t*)&h1;
        pk.z = *(uint32_t*)&h2; pk.w = *(uint32_t*)&h3;
        *(uint4*)(out + i) = pk;
    }
}

// ---------------- adaLN ---------------------------------------------------------
__global__ void ada_kernel(const float* __restrict__ c,
                           const float* __restrict__ Wa, const float* __restrict__ ba,
                           const float* __restrict__ Wc, const float* __restrict__ bc,
                           float* __restrict__ outA, float* __restrict__ outC) {
    __shared__ float scs[BB * DD];
    int tid = threadIdx.x;
    for (int idx = tid; idx < BB * DD; idx += 256) {
        float v = c[idx];
        scs[idx] = v / (1.0f + __expf(-v));
    }
    __syncthreads();
    const float* W = blockIdx.y ? Wc : Wa;
    const float* bias = blockIdx.y ? bc : ba;
    float* out = blockIdx.y ? outC : outA;
    int col = blockIdx.x * 256 + tid;
    float a0 = 0.f, a1 = 0.f, a2 = 0.f, a3 = 0.f;
    for (int k = 0; k < DD; k++) {
        float w = __ldg(&W[(size_t)k * 6144 + col]);
        a0 += scs[k] * w;
        a1 += scs[DD + k] * w;
        a2 += scs[2 * DD + k] * w;
        a3 += scs[3 * DD + k] * w;
    }
    float bv = bias[col];
    out[col] = a0 + bv;
    out[6144 + col] = a1 + bv;
    out[2 * 6144 + col] = a2 + bv;
    out[3 * 6144 + col] = a3 + bv;
}

// ---------------- LayerNorm + modulate, fp16 output ------------------------------
__global__ void ln_mod_kernel(const float* __restrict__ xs, const float* __restrict__ cs,
                              const float* __restrict__ adaA, const float* __restrict__ adaC,
                              int sofs, __half* __restrict__ out) {
    int r = blockIdx.x;
    int tid = threadIdx.x;
    const float* src;
    const float* ada;
    int b;
    if (r < XROWS) { b = r >> 10; src = xs + (size_t)r * DD; ada = adaA; }
    else { int rc = r - XROWS; b = rc / NC; src = cs + (size_t)rc * DD; ada = adaC; }

    float4 v = *(const float4*)(src + tid * 4);
    float s = v.x + v.y + v.z + v.w;
    float sq = v.x * v.x + v.y * v.y + v.z * v.z + v.w * v.w;
    #pragma unroll
    for (int o = 16; o; o >>= 1) {
        s += __shfl_xor_sync(0xffffffffu, s, o);
        sq += __shfl_xor_sync(0xffffffffu, sq, o);
    }
    __shared__ float rs[8], rq[8];
    __shared__ float smu, srstd;
    int w = tid >> 5;
    if ((tid & 31) == 0) { rs[w] = s; rq[w] = sq; }
    __syncthreads();
    if (tid == 0) {
        float ts = 0.f, tq = 0.f;
        #pragma unroll
        for (int i = 0; i < 8; i++) { ts += rs[i]; tq += rq[i]; }
        float mu = ts * (1.0f / DD);
        float var = tq * (1.0f / DD) - mu * mu;
        smu = mu;
        srstd = rsqrtf(var + 1e-6f);
    }
    __syncthreads();
    float mu = smu, rstd = srstd;
    const float* ap = ada + (size_t)b * 6144 + sofs;
    int col = tid * 4;
    float4 sh = *(const float4*)(ap + col);
    float4 sc = *(const float4*)(ap + 1024 + col);
    float o0 = (v.x - mu) * rstd * (1.0f + sc.x) + sh.x;
    float o1 = (v.y - mu) * rstd * (1.0f + sc.y) + sh.y;
    float o2 = (v.z - mu) * rstd * (1.0f + sc.z) + sh.z;
    float o3 = (v.w - mu) * rstd * (1.0f + sc.w) + sh.w;
    __half2 p0 = __floats2half2_rn(o0, o1);
    __half2 p1 = __floats2half2_rn(o2, o3);
    uint2 pk; pk.x = *(uint32_t*)&p0; pk.y = *(uint32_t*)&p1;
    *(uint2*)(out + (size_t)r * DD + col) = pk;
}

// ---------------- fused FP16 GEMM pair -------------------------------------------
// 128x128 block, BK=32, 256 threads, 2-stage cp.async, ldmatrix frags.
// mode 0: ->half C, 1: GELU->half C, 2: float C = res + gate*(acc+bias)
__global__ __launch_bounds__(256, 2) void gemm_f16_fused(
    const __half* __restrict__ A1, const __half* __restrict__ B1, const float* __restrict__ bias1,
    void* __restrict__ C1, int M1,
    const __half* __restrict__ A2, const __half* __restrict__ B2, const float* __restrict__ bias2,
    void* __restrict__ C2, int M2,
    int N, int K, int ny1,
    const float* __restrict__ res1, const float* __restrict__ gate1, int rpb1,
    const float* __restrict__ res2, const float* __restrict__ gate2, int rpb2,
    int gofs, int mode) {
    __shared__ __half As[2][128][40];
    __shared__ __half Bs[2][32][136];

    const int tid = threadIdx.x;
    const int lane = tid & 31, wid = tid >> 5;
    const int g = lane >> 2, tg = lane & 3;
    const int rlm = (lane & 7) + ((lane >> 3) & 1) * 8;
    const int clm = (lane >> 4) * 8;
    const int mbase = (wid >> 2) * 64, nbase = (wid & 3) * 32;

    const __half *A, *B;
    const float *bias, *res, *gate;
    void* C;
    int M, rpb, row0;
    if ((int)blockIdx.y < ny1) {
        A = A1; B = B1; bias = bias1; C = C1; M = M1; res = res1; gate = gate1; rpb = rpb1;
        row0 = blockIdx.y * 128;
    } else {
        A = A2; B = B2; bias = bias2; C = C2; M = M2; res = res2; gate = gate2; rpb = rpb2;
        row0 = (blockIdx.y - ny1) * 128;
    }
    const int col0 = blockIdx.x * 128;

    float acc[4][4][4];
    #pragma unroll
    for (int mt = 0; mt < 4; mt++)
        #pragma unroll
        for (int nt = 0; nt < 4; nt++)
            #pragma unroll
            for (int i = 0; i < 4; i++) acc[mt][nt][i] = 0.f;

    const int ntiles = K >> 5;

    auto load_stage = [&](int t, int s) {
        #pragma unroll
        for (int i = 0; i < 2; i++) {
            int c = i * 256 + tid;
            int row = c >> 2, q = c & 3;
            bool v = (row0 + row) < M;
            cp16(&As[s][row][q * 8], A + (size_t)(v ? row0 + row : 0) * K + t * 32 + q * 8, v);
        }
        #pragma unroll
        for (int i = 0; i < 2; i++) {
            int c = i * 256 + tid;
            int row = c >> 4, q = c & 15;
            cp16(&Bs[s][row][q * 8], B + (size_t)(t * 32 + row) * N + col0 + q * 8, true);
        }
        asm volatile("cp.async.commit_group;");
    };

    load_stage(0, 0);

    for (int t = 0; t < ntiles; t++) {
        if (t + 1 < ntiles) {
            load_stage(t + 1, (t + 1) & 1);
            asm volatile("cp.async.wait_group 1;");
        } else {
            asm volatile("cp.async.wait_group 0;");
        }
        __syncthreads();
        const int s = t & 1;
        #pragma unroll
        for (int ks = 0; ks < 32; ks += 16) {
            uint32_t bf[4][2];
            #pragma unroll
            for (int p = 0; p < 2; p++) {
                uint32_t bb[4];
                ldsm4t(bb, (uint32_t)__cvta_generic_to_shared(
                    &Bs[s][ks + rlm][nbase + p * 16 + clm]));
                bf[2 * p][0] = bb[0]; bf[2 * p][1] = bb[1];
                bf[2 * p + 1][0] = bb[2]; bf[2 * p + 1][1] = bb[3];
            }
            #pragma unroll
            for (int mt = 0; mt < 4; mt++) {
                uint32_t af[4];
                ldsm4(af, (uint32_t)__cvta_generic_to_shared(
                    &As[s][mbase + mt * 16 + rlm][ks + clm]));
                #pragma unroll
                for (int nt = 0; nt < 4; nt++)
                    mma_f16(acc[mt][nt][0], acc[mt][nt][1], acc[mt][nt][2], acc[mt][nt][3],
                            af[0], af[1], af[2], af[3], bf[nt][0], bf[nt][1]);
            }
        }
        __syncthreads();
    }

    // epilogue (accum layout: c0,c1 = row g cols 2tg,2tg+1; c2,c3 = row g+8)
    #pragma unroll
    for (int mt = 0; mt < 4; mt++) {
        int rA = row0 + mbase + mt * 16 + g;
        int rB = rA + 8;
        #pragma unroll
        for (int nt = 0; nt < 4; nt++) {
            int col = col0 + nbase + nt * 8 + tg * 2;
            float2 bv = *(const float2*)&bias[col];
            float v0 = acc[mt][nt][0] + bv.x;
            float v1 = acc[mt][nt][1] + bv.y;
            float v2 = acc[mt][nt][2] + bv.x;
            float v3 = acc[mt][nt][3] + bv.y;
            if (mode == 1) {
                v0 = gelu_tanh(v0); v1 = gelu_tanh(v1);
                v2 = gelu_tanh(v2); v3 = gelu_tanh(v3);
            }
            if (mode == 2) {
                if (rA < M) {
                    int bb = rA / rpb;
                    float2 gg = *(const float2*)&gate[(size_t)bb * 6144 + gofs + col];
                    float2 rr = *(const float2*)&res[(size_t)rA * N + col];
                    *(float2*)((float*)C + (size_t)rA * N + col) =
                        make_float2(rr.x + gg.x * v0, rr.y + gg.y * v1);
                }
                if (rB < M) {
                    int bb = rB / rpb;
                    float2 gg = *(const float2*)&gate[(size_t)bb * 6144 + gofs + col];
                    float2 rr = *(const float2*)&res[(size_t)rB * N + col];
                    *(float2*)((float*)C + (size_t)rB * N + col) =
                        make_float2(rr.x + gg.x * v2, rr.y + gg.y * v3);
                }
            } else {
                if (rA < M) {
                    __half2 h = __floats2half2_rn(v0, v1);
                    *(__half2*)((__half*)C + (size_t)rA * N + col) = h;
                }
                if (rB < M) {
                    __half2 h = __floats2half2_rn(v2, v3);
                    *(__half2*)((__half*)C + (size_t)rB * N + col) = h;
                }
            }
        }
    }
}

// ---------------- fp16 tensor-core joint flash attention -------------------------
// grid (18, H, B), block 128 (4 warps x 16 q-rows). BK=32 keys, 2-stage cp.async.
__global__ void attn_kernel(const __half* __restrict__ qkvx,
                            const __half* __restrict__ qkvc,
                            __half* __restrict__ out) {
    __shared__ __half Qs[64][72];
    __shared__ __half Ks[2][32][72];
    __shared__ __half Vs[2][32][72];

    const int qt = blockIdx.x, h = blockIdx.y, b = blockIdx.z;
    const int tid = threadIdx.x;
    const int lane = tid & 31, wid = tid >> 5;
    const int g = lane >> 2, tg = lane & 3;
    const int rlm = (lane & 7) + ((lane >> 3) & 1) * 8;  // A/trans-B row pattern
    const int clm = (lane >> 4) * 8;
    const int rk = (lane & 7) + ((lane >> 4) << 3);      // K(non-trans B): key row
    const int ck = ((lane >> 3) & 1) * 8;                //               k-half
    const int q0 = qt * 64;

    auto load_kv = [&](int kt, int st) {
        #pragma unroll
        for (int i = 0; i < 2; i++) {
            int c = i * 128 + tid;
            int r = c >> 3, q = c & 7;
            int key = kt * 32 + r;
            bool v = key < S_TOT;
            const __half* rp = qkvx;
            if (v) rp = (key < NN) ? (qkvx + (size_t)(b * NN + key) * 3072)
                                   : (qkvc + (size_t)(b * NC + (key - NN)) * 3072);
            cp16(&Ks[st][r][q * 8], rp + 1024 + h * HD + q * 8, v);
            cp16(&Vs[st][r][q * 8], rp + 2048 + h * HD + q * 8, v);
        }
        asm volatile("cp.async.commit_group;");
    };

    // prologue: Q + KV(0) in group 0
    #pragma unroll
    for (int i = 0; i < 4; i++) {
        int c = i * 128 + tid;
        int r = c >> 3, q = c & 7;
        int qi = q0 + r;
        bool v = qi < S_TOT;
        const __half* rp = qkvx;
        if (v) rp = (qi < NN) ? (qkvx + (size_t)(b * NN + qi) * 3072)
                              : (qkvc + (size_t)(b * NC + (qi - NN)) * 3072);
        cp16(&Qs[r][q * 8], rp + h * HD + q * 8, v);
    }
    load_kv(0, 0);
    asm volatile("cp.async.wait_group 0;");
    __syncthreads();

    // Q frags (m16n8k16 A), scaled by hd^-0.5 = 0.125
    uint32_t qf[4][4];
    {
        const __half2 sc = __floats2half2_rn(0.125f, 0.125f);
        int r0 = wid * 16 + rlm;
        #pragma unroll
        for (int ks = 0; ks < 4; ks++) {
            ldsm4(qf[ks], (uint32_t)__cvta_generic_to_shared(&Qs[r0][ks * 16 + clm]));
            #pragma unroll
            for (int i = 0; i < 4; i++) {
                __half2 hv = *(__half2*)&qf[ks][i];
                hv = __hmul2(hv, sc);
                qf[ks][i] = *(uint32_t*)&hv;
            }
        }
    }

    float o[8][4];
    #pragma unroll
    for (int nt = 0; nt < 8; nt++)
        #pragma unroll
        for (int i = 0; i < 4; i++) o[nt][i] = 0.f;
    float m0 = -1e30f, m1 = -1e30f, l0 = 0.f, l1 = 0.f;

    const int nkt = (S_TOT + 31) / 32;  // 35

    for (int kt = 0; kt < nkt; kt++) {
        if (kt + 1 < nkt) {
            load_kv(kt + 1, (kt + 1) & 1);
            asm volatile("cp.async.wait_group 1;");
        } else {
            asm volatile("cp.async.wait_group 0;");
        }
        __syncthreads();
        const int s = kt & 1;

        // S = Q @ K^T : 4 key-blocks (nt) x 4 k-slices
        float sa[4][4];
        #pragma unroll
        for (int nt = 0; nt < 4; nt++)
            #pragma unroll
            for (int i = 0; i < 4; i++) sa[nt][i] = 0.f;
        #pragma unroll
        for (int ks = 0; ks < 4; ks++) {
            #pragma unroll
            for (int p = 0; p < 2; p++) {
                uint32_t kb[4];
                ldsm4(kb, (uint32_t)__cvta_generic_to_shared(
                    &Ks[s][p * 16 + rk][ks * 16 + ck]));
                mma_f16(sa[2 * p][0], sa[2 * p][1], sa[2 * p][2], sa[2 * p][3],
                        qf[ks][0], qf[ks][1], qf[ks][2], qf[ks][3], kb[0], kb[1]);
                mma_f16(sa[2 * p + 1][0], sa[2 * p + 1][1], sa[2 * p + 1][2], sa[2 * p + 1][3],
                        qf[ks][0], qf[ks][1], qf[ks][2], qf[ks][3], kb[2], kb[3]);
            }
        }

        // mask OOB keys
        #pragma unroll
        for (int nt = 0; nt < 4; nt++) {
            int k0 = kt * 32 + nt * 8 + 2 * tg;
            if (k0 >= S_TOT) { sa[nt][0] = -1e30f; sa[nt][2] = -1e30f; }
            if (k0 + 1 >= S_TOT) { sa[nt][1] = -1e30f; sa[nt][3] = -1e30f; }
        }

        // online softmax (rows g, g+8; quad-shfl reduce)
        float mx0 = -1e30f, mx1 = -1e30f;
        #pragma unroll
        for (int nt = 0; nt < 4; nt++) {
            mx0 = fmaxf(mx0, fmaxf(sa[nt][0], sa[nt][1]));
            mx1 = fmaxf(mx1, fmaxf(sa[nt][2], sa[nt][3]));
        }
        mx0 = fmaxf(mx0, __shfl_xor_sync(0xffffffffu, mx0, 1));
        mx0 = fmaxf(mx0, __shfl_xor_sync(0xffffffffu, mx0, 2));
        mx1 = fmaxf(mx1, __shfl_xor_sync(0xffffffffu, mx1, 1));
        mx1 = fmaxf(mx1, __shfl_xor_sync(0xffffffffu, mx1, 2));
        float mn0 = fmaxf(m0, mx0), mn1 = fmaxf(m1, mx1);
        float sc0 = __expf(m0 - mn0), sc1 = __expf(m1 - mn1);
        float sum0 = 0.f, sum1 = 0.f;
        #pragma unroll
        for (int nt = 0; nt < 4; nt++) {
            sa[nt][0] = __expf(sa[nt][0] - mn0);
            sa[nt][1] = __expf(sa[nt][1] - mn0);
            sa[nt][2] = __expf(sa[nt][2] - mn1);
            sa[nt][3] = __expf(sa[nt][3] - mn1);
            sum0 += sa[nt][0] + sa[nt][1];
            sum1 += sa[nt][2] + sa[nt][3];
        }
        sum0 += __shfl_xor_sync(0xffffffffu, sum0, 1);
        sum0 += __shfl_xor_sync(0xffffffffu, sum0, 2);
        sum1 += __shfl_xor_sync(0xffffffffu, sum1, 1);
        sum1 += __shfl_xor_sync(0xffffffffu, sum1, 2);
        l0 = l0 * sc0 + sum0;
        l1 = l1 * sc1 + sum1;
        m0 = mn0; m1 = mn1;
        #pragma unroll
        for (int nt = 0; nt < 8; nt++) {
            o[nt][0] *= sc0; o[nt][1] *= sc0;
            o[nt][2] *= sc1; o[nt][3] *= sc1;
        }

        // P -> fp16 A-frags (accum layout == A-frag layout)
        uint32_t pf[2][4];
        #pragma unroll
        for (int k2 = 0; k2 < 2; k2++) {
            pf[k2][0] = pk_f16(sa[2 * k2][0], sa[2 * k2][1]);
            pf[k2][1] = pk_f16(sa[2 * k2][2], sa[2 * k2][3]);
            pf[k2][2] = pk_f16(sa[2 * k2 + 1][0], sa[2 * k2 + 1][1]);
            pf[k2][3] = pk_f16(sa[2 * k2 + 1][2], sa[2 * k2 + 1][3]);
        }
        // O += P @ V  (V via trans ldmatrix: d-block pairs)
        #pragma unroll
        for (int k2 = 0; k2 < 2; k2++) {
            #pragma unroll
            for (int p = 0; p < 4; p++) {
                uint32_t vb[4];
                ldsm4t(vb, (uint32_t)__cvta_generic_to_shared(
                    &Vs[s][k2 * 16 + rlm][p * 16 + clm]));
                mma_f16(o[2 * p][0], o[2 * p][1], o[2 * p][2], o[2 * p][3],
                        pf[k2][0], pf[k2][1], pf[k2][2], pf[k2][3], vb[0], vb[1]);
                mma_f16(o[2 * p + 1][0], o[2 * p + 1][1], o[2 * p + 1][2], o[2 * p + 1][3],
                        pf[k2][0], pf[k2][1], pf[k2][2], pf[k2][3], vb[2], vb[3]);
            }
        }
        __syncthreads();
    }

    // write fp16 output
    float inv0 = 1.0f / l0, inv1 = 1.0f / l1;
    int r0 = q0 + wid * 16 + g;
    int r1 = r0 + 8;
    #pragma unroll
    for (int nt = 0; nt < 8; nt++) {
        int col = h * HD + nt * 8 + 2 * tg;
        if (r0 < S_TOT) {
            int rowg = (r0 < NN) ? (b * NN + r0) : (XROWS + b * NC + (r0 - NN));
            *(__half2*)&out[(size_t)rowg * DD + col] =
                __floats2half2_rn(o[nt][0] * inv0, o[nt][1] * inv0);
        }
        if (r1 < S_TOT) {
            int rowg = (r1 < NN) ? (b * NN + r1) : (XROWS + b * NC + (r1 - NN));
            *(__half2*)&out[(size_t)rowg * DD + col] =
                __floats2half2_rn(o[nt][2] * inv1, o[nt][3] * inv1);
        }
    }
}

// ---------------- launcher ----------------
extern "C" void kernel_launch(void* const* d_in, const int* in_sizes, int n_in,
                              void* d_out, int out_size) {
    const float* x       = (const float*)d_in[0];
    const float* cond    = (const float*)d_in[1];
    const float* c       = (const float*)d_in[2];
    const float* W_ada   = (const float*)d_in[3];
    const float* b_ada   = (const float*)d_in[4];
    const float* W_ada_c = (const float*)d_in[5];
    const float* b_ada_c = (const float*)d_in[6];
    const float* W_qkv   = (const float*)d_in[7];
    const float* b_qkv   = (const float*)d_in[8];
    const float* W_proj  = (const float*)d_in[9];
    const float* b_proj  = (const float*)d_in[10];
    const float* W_qkv_c = (const float*)d_in[11];
    const float* b_qkv_c = (const float*)d_in[12];
    const float* W_proj_c= (const float*)d_in[13];
    const float* b_proj_c= (const float*)d_in[14];
    const float* W_fc1   = (const float*)d_in[15];
    const float* b_fc1   = (const float*)d_in[16];
    const float* W_fc2   = (const float*)d_in[17];
    const float* b_fc2   = (const float*)d_in[18];
    const float* W_fc1_c = (const float*)d_in[19];
    const float* b_fc1_c = (const float*)d_in[20];
    const float* W_fc2_c = (const float*)d_in[21];
    const float* b_fc2_c = (const float*)d_in[22];
    float* out = (float*)d_out;

    float *adaA, *adaC, *xmid, *cmid;
    __half *xt, *qkvx, *qkvc, *attn, *hx, *hc;
    __half *wqkv, *wqkvc, *wproj, *wprojc, *wfc1, *wfc1c, *wfc2, *wfc2c;
    cudaGetSymbolAddress((void**)&adaA, g_adaA);
    cudaGetSymbolAddress((void**)&adaC, g_adaC);
    cudaGetSymbolAddress((void**)&xmid, g_xmid);
    cudaGetSymbolAddress((void**)&cmid, g_cmid);
    cudaGetSymbolAddress((void**)&xt,   h_xt);
    cudaGetSymbolAddress((void**)&qkvx, h_qkvx);
    cudaGetSymbolAddress((void**)&qkvc, h_qkvc);
    cudaGetSymbolAddress((void**)&attn, h_attn);
    cudaGetSymbolAddress((void**)&hx,   h_hx);
    cudaGetSymbolAddress((void**)&hc,   h_hc);
    cudaGetSymbolAddress((void**)&wqkv, h_Wqkv);
    cudaGetSymbolAddress((void**)&wqkvc,h_Wqkvc);
    cudaGetSymbolAddress((void**)&wproj,h_Wproj);
    cudaGetSymbolAddress((void**)&wprojc,h_Wprojc);
    cudaGetSymbolAddress((void**)&wfc1, h_Wfc1);
    cudaGetSymbolAddress((void**)&wfc1c,h_Wfc1c);
    cudaGetSymbolAddress((void**)&wfc2, h_Wfc2);
    cudaGetSymbolAddress((void**)&wfc2c,h_Wfc2c);

    auto cvt = [&](const float* src, __half* dst, int n) {
        f2h_kernel<<<(n / 8 + 255) / 256, 256>>>(src, dst, n);
    };
    cvt(W_qkv,   wqkv,  DD * 3 * DD);
    cvt(W_qkv_c, wqkvc, DD * 3 * DD);
    cvt(W_proj,  wproj, DD * DD);
    cvt(W_proj_c,wprojc,DD * DD);
    cvt(W_fc1,   wfc1,  DD * DFF);
    cvt(W_fc1_c, wfc1c, DD * DFF);
    cvt(W_fc2,   wfc2,  DFF * DD);
    cvt(W_fc2_c, wfc2c, DFF * DD);

    const __half* xtc = xt + (size_t)XROWS * DD;
    const __half* attc = attn + (size_t)XROWS * DD;
    const int NY1 = XROWS / 128;                 // 32
    const int NY2 = (CROWS + 127) / 128;         // 3

    // 1. adaLN
    ada_kernel<<<dim3(6144 / 256, 2), 256>>>(c, W_ada, b_ada, W_ada_c, b_ada_c, adaA, adaC);
    // 2. LN + modulate (MSA) -> fp16
    ln_mod_kernel<<<TROWS, 256>>>(x, cond, adaA, adaC, 0, xt);
    // 3. fused QKV GEMMs -> fp16 qkv
    gemm_f16_fused<<<dim3(3072 / 128, NY1 + NY2), 256>>>(
        xt, wqkv, b_qkv, qkvx, XROWS,
        xtc, wqkvc, b_qkv_c, qkvc, CROWS,
        3072, 1024, NY1, nullptr, nullptr, 1, nullptr, nullptr, 1, 0, 0);
    // 4. joint attention -> fp16
    attn_kernel<<<dim3((S_TOT + 63) / 64, HH, BB), 128>>>(qkvx, qkvc, attn);
    // 5. fused proj + gated residual -> fp32 xmid/cmid
    gemm_f16_fused<<<dim3(1024 / 128, NY1 + NY2), 256>>>(
        attn, wproj, b_proj, xmid, XROWS,
        attc, wprojc, b_proj_c, cmid, CROWS,
        1024, 1024, NY1, x, adaA, NN, cond, adaC, NC, 2048, 2);
    // 6. LN + modulate (MLP) -> fp16
    ln_mod_kernel<<<TROWS, 256>>>(xmid, cmid, adaA, adaC, 3072, xt);
    // 7. fused fc1 + GELU -> fp16 hidden
    gemm_f16_fused<<<dim3(DFF / 128, NY1 + NY2), 256>>>(
        xt, wfc1, b_fc1, hx, XROWS,
        xtc, wfc1c, b_fc1_c, hc, CROWS,
        DFF, 1024, NY1, nullptr, nullptr, 1, nullptr, nullptr, 1, 0, 1);
    // 8. fused fc2 + gated residual -> fp32 d_out
    gemm_f16_fused<<<dim3(1024 / 128, NY1 + NY2), 256>>>(
        hx, wfc2, b_fc2, out, XROWS,
        hc, wfc2c, b_fc2_c, out + (size_t)XROWS * DD, CROWS,
        1024, DFF, NY1, xmid, adaA, NN, cmid, adaC, NC, 5120, 2);
}

// round 9
// speedup vs baseline: 6.9865x; 1.0261x over previous
#include <cuda_runtime.h>
#include <cuda_fp16.h>
#include <math.h>
#include <stdint.h>

// Shapes (fixed per reference)
#define BB 4
#define NN 1024
#define NC 77
#define DD 1024
#define HH 16
#define HD 64
#define DFF 4096
#define S_TOT (NN + NC)        // 1101
#define XROWS (BB * NN)        // 4096
#define CROWS (BB * NC)        // 308
#define TROWS (XROWS + CROWS)  // 4404

// ---------------- scratch ----------------
__device__ float g_adaA[BB * 6 * DD];
__device__ float g_adaC[BB * 6 * DD];
__device__ float g_xmid[XROWS * DD];
__device__ float g_cmid[CROWS * DD];
// fp16 activations
__device__ __half h_xt[TROWS * DD];
__device__ __half h_qkvx[XROWS * 3 * DD];
__device__ __half h_qkvc[CROWS * 3 * DD];
__device__ __half h_attn[TROWS * DD];
__device__ __half h_hx[XROWS * DFF];
__device__ __half h_hc[CROWS * DFF];
// fp16 weights (same [K][N] layout as inputs)
__device__ __half h_Wqkv[DD * 3 * DD];
__device__ __half h_Wqkvc[DD * 3 * DD];
__device__ __half h_Wproj[DD * DD];
__device__ __half h_Wprojc[DD * DD];
__device__ __half h_Wfc1[DD * DFF];
__device__ __half h_Wfc1c[DD * DFF];
__device__ __half h_Wfc2[DFF * DD];
__device__ __half h_Wfc2c[DFF * DD];

// ---------------- helpers ----------------
__device__ __forceinline__ float gelu_tanh(float x) {
    float x3 = x * x * x;
    float t = tanhf(0.7978845608028654f * (x + 0.044715f * x3));
    return 0.5f * x * (1.0f + t);
}

__device__ __forceinline__ void mma_f16(float& c0, float& c1, float& c2, float& c3,
                                        uint32_t a0, uint32_t a1, uint32_t a2, uint32_t a3,
                                        uint32_t b0, uint32_t b1) {
    asm volatile("mma.sync.aligned.m16n8k16.row.col.f32.f16.f16.f32 "
                 "{%0,%1,%2,%3}, {%4,%5,%6,%7}, {%8,%9}, {%0,%1,%2,%3};"
                 : "+f"(c0), "+f"(c1), "+f"(c2), "+f"(c3)
                 : "r"(a0), "r"(a1), "r"(a2), "r"(a3), "r"(b0), "r"(b1));
}

__device__ __forceinline__ void ldsm4(uint32_t* r, uint32_t a) {
    asm volatile("ldmatrix.sync.aligned.m8n8.x4.shared.b16 {%0,%1,%2,%3}, [%4];"
                 : "=r"(r[0]), "=r"(r[1]), "=r"(r[2]), "=r"(r[3]) : "r"(a));
}
__device__ __forceinline__ void ldsm4t(uint32_t* r, uint32_t a) {
    asm volatile("ldmatrix.sync.aligned.m8n8.x4.trans.shared.b16 {%0,%1,%2,%3}, [%4];"
                 : "=r"(r[0]), "=r"(r[1]), "=r"(r[2]), "=r"(r[3]) : "r"(a));
}

__device__ __forceinline__ uint32_t pk_f16(float lo, float hi) {
    __half2 h = __floats2half2_rn(lo, hi);
    return *(uint32_t*)&h;
}

__device__ __forceinline__ void cp16(void* sm, const void* g, bool v) {
    uint32_t s = (uint32_t)__cvta_generic_to_shared(sm);
    int sz = v ? 16 : 0;
    asm volatile("cp.async.cg.shared.global [%0], [%1], 16, %2;" :: "r"(s), "l"(g), "r"(sz));
}

// ---------------- fused fp32->fp16 convert (all weights, one launch) ------------
struct CvtSeg { const float* src; __half* dst; int n; };
struct CvtArgs { CvtSeg seg[8]; };

__global__ void f2h_all_kernel(CvtArgs a) {
    CvtSeg s = a.seg[blockIdx.y];
    const int stride = gridDim.x * blockDim.x * 8;
    for (int i = (blockIdx.x * blockDim.x + threadIdx.x) * 8; i < s.n; i += stride) {
        float4 v0 = *(const float4*)(s.src + i);
        float4 v1 = *(const float4*)(s.src + i + 4);
        __half2 h0 = __floats2half2_rn(v0.x, v0.y);
        __half2 h1 = __floats2half2_rn(v0.z, v0.w);
        __half2 h2 = __floats2half2_rn(v1.x, v1.y);
        __half2 h3 = __floats2half2_rn(v1.z, v1.w);
        uint4 pk;
        pk.x = *(uint32_t*)&h0; pk.y = *(uint32_t*)&h1;
        pk.z = *(uint32_t*)&h2; pk.w = *(uint32_t*)&h3;
        *(uint4*)(s.dst + i) = pk;
    }
}

// ---------------- adaLN ---------------------------------------------------------
__global__ void ada_kernel(const float* __restrict__ c,
                           const float* __restrict__ Wa, const float* __restrict__ ba,
                           const float* __restrict__ Wc, const float* __restrict__ bc,
                           float* __restrict__ outA, float* __restrict__ outC) {
    __shared__ float scs[BB * DD];
    int tid = threadIdx.x;
    for (int idx = tid; idx < BB * DD; idx += 256) {
        float v = c[idx];
        scs[idx] = v / (1.0f + __expf(-v));
    }
    __syncthreads();
    const float* W = blockIdx.y ? Wc : Wa;
    const float* bias = blockIdx.y ? bc : ba;
    float* out = blockIdx.y ? outC : outA;
    int col = blockIdx.x * 256 + tid;
    float a0 = 0.f, a1 = 0.f, a2 = 0.f, a3 = 0.f;
    for (int k = 0; k < DD; k++) {
        float w = __ldg(&W[(size_t)k * 6144 + col]);
        a0 += scs[k] * w;
        a1 += scs[DD + k] * w;
        a2 += scs[2 * DD + k] * w;
        a3 += scs[3 * DD + k] * w;
    }
    float bv = bias[col];
    out[col] = a0 + bv;
    out[6144 + col] = a1 + bv;
    out[2 * 6144 + col] = a2 + bv;
    out[3 * 6144 + col] = a3 + bv;
}

// ---------------- LayerNorm + modulate, fp16 output ------------------------------
__global__ void ln_mod_kernel(const float* __restrict__ xs, const float* __restrict__ cs,
                              const float* __restrict__ adaA, const float* __restrict__ adaC,
                              int sofs, __half* __restrict__ out) {
    int r = blockIdx.x;
    int tid = threadIdx.x;
    const float* src;
    const float* ada;
    int b;
    if (r < XROWS) { b = r >> 10; src = xs + (size_t)r * DD; ada = adaA; }
    else { int rc = r - XROWS; b = rc / NC; src = cs + (size_t)rc * DD; ada = adaC; }

    float4 v = *(const float4*)(src + tid * 4);
    float s = v.x + v.y + v.z + v.w;
    float sq = v.x * v.x + v.y * v.y + v.z * v.z + v.w * v.w;
    #pragma unroll
    for (int o = 16; o; o >>= 1) {
        s += __shfl_xor_sync(0xffffffffu, s, o);
        sq += __shfl_xor_sync(0xffffffffu, sq, o);
    }
    __shared__ float rs[8], rq[8];
    __shared__ float smu, srstd;
    int w = tid >> 5;
    if ((tid & 31) == 0) { rs[w] = s; rq[w] = sq; }
    __syncthreads();
    if (tid == 0) {
        float ts = 0.f, tq = 0.f;
        #pragma unroll
        for (int i = 0; i < 8; i++) { ts += rs[i]; tq += rq[i]; }
        float mu = ts * (1.0f / DD);
        float var = tq * (1.0f / DD) - mu * mu;
        smu = mu;
        srstd = rsqrtf(var + 1e-6f);
    }
    __syncthreads();
    float mu = smu, rstd = srstd;
    const float* ap = ada + (size_t)b * 6144 + sofs;
    int col = tid * 4;
    float4 sh = *(const float4*)(ap + col);
    float4 sc = *(const float4*)(ap + 1024 + col);
    float o0 = (v.x - mu) * rstd * (1.0f + sc.x) + sh.x;
    float o1 = (v.y - mu) * rstd * (1.0f + sc.y) + sh.y;
    float o2 = (v.z - mu) * rstd * (1.0f + sc.z) + sh.z;
    float o3 = (v.w - mu) * rstd * (1.0f + sc.w) + sh.w;
    __half2 p0 = __floats2half2_rn(o0, o1);
    __half2 p1 = __floats2half2_rn(o2, o3);
    uint2 pk; pk.x = *(uint32_t*)&p0; pk.y = *(uint32_t*)&p1;
    *(uint2*)(out + (size_t)r * DD + col) = pk;
}

// ---------------- fused FP16 GEMM pair (proven round-6 version) ------------------
// 128x128 block, BK=32, 256 threads, 2-stage cp.async, ldmatrix frags.
// mode 0: ->half C, 1: GELU->half C, 2: float C = res + gate*(acc+bias)
__global__ __launch_bounds__(256, 2) void gemm_f16_fused(
    const __half* __restrict__ A1, const __half* __restrict__ B1, const float* __restrict__ bias1,
    void* __restrict__ C1, int M1,
    const __half* __restrict__ A2, const __half* __restrict__ B2, const float* __restrict__ bias2,
    void* __restrict__ C2, int M2,
    int N, int K, int ny1,
    const float* __restrict__ res1, const float* __restrict__ gate1, int rpb1,
    const float* __restrict__ res2, const float* __restrict__ gate2, int rpb2,
    int gofs, int mode) {
    __shared__ __half As[2][128][40];
    __shared__ __half Bs[2][32][136];

    const int tid = threadIdx.x;
    const int lane = tid & 31, wid = tid >> 5;
    const int g = lane >> 2, tg = lane & 3;
    const int rlm = (lane & 7) + ((lane >> 3) & 1) * 8;
    const int clm = (lane >> 4) * 8;
    const int mbase = (wid >> 2) * 64, nbase = (wid & 3) * 32;

    const __half *A, *B;
    const float *bias, *res, *gate;
    void* C;
    int M, rpb, row0;
    if ((int)blockIdx.y < ny1) {
        A = A1; B = B1; bias = bias1; C = C1; M = M1; res = res1; gate = gate1; rpb = rpb1;
        row0 = blockIdx.y * 128;
    } else {
        A = A2; B = B2; bias = bias2; C = C2; M = M2; res = res2; gate = gate2; rpb = rpb2;
        row0 = (blockIdx.y - ny1) * 128;
    }
    const int col0 = blockIdx.x * 128;

    float acc[4][4][4];
    #pragma unroll
    for (int mt = 0; mt < 4; mt++)
        #pragma unroll
        for (int nt = 0; nt < 4; nt++)
            #pragma unroll
            for (int i = 0; i < 4; i++) acc[mt][nt][i] = 0.f;

    const int ntiles = K >> 5;

    auto load_stage = [&](int t, int s) {
        #pragma unroll
        for (int i = 0; i < 2; i++) {
            int c = i * 256 + tid;
            int row = c >> 2, q = c & 3;
            bool v = (row0 + row) < M;
            cp16(&As[s][row][q * 8], A + (size_t)(v ? row0 + row : 0) * K + t * 32 + q * 8, v);
        }
        #pragma unroll
        for (int i = 0; i < 2; i++) {
            int c = i * 256 + tid;
            int row = c >> 4, q = c & 15;
            cp16(&Bs[s][row][q * 8], B + (size_t)(t * 32 + row) * N + col0 + q * 8, true);
        }
        asm volatile("cp.async.commit_group;");
    };

    load_stage(0, 0);

    for (int t = 0; t < ntiles; t++) {
        if (t + 1 < ntiles) {
            load_stage(t + 1, (t + 1) & 1);
            asm volatile("cp.async.wait_group 1;");
        } else {
            asm volatile("cp.async.wait_group 0;");
        }
        __syncthreads();
        const int s = t & 1;
        #pragma unroll
        for (int ks = 0; ks < 32; ks += 16) {
            uint32_t bf[4][2];
            #pragma unroll
            for (int p = 0; p < 2; p++) {
                uint32_t bb[4];
                ldsm4t(bb, (uint32_t)__cvta_generic_to_shared(
                    &Bs[s][ks + rlm][nbase + p * 16 + clm]));
                bf[2 * p][0] = bb[0]; bf[2 * p][1] = bb[1];
                bf[2 * p + 1][0] = bb[2]; bf[2 * p + 1][1] = bb[3];
            }
            #pragma unroll
            for (int mt = 0; mt < 4; mt++) {
                uint32_t af[4];
                ldsm4(af, (uint32_t)__cvta_generic_to_shared(
                    &As[s][mbase + mt * 16 + rlm][ks + clm]));
                #pragma unroll
                for (int nt = 0; nt < 4; nt++)
                    mma_f16(acc[mt][nt][0], acc[mt][nt][1], acc[mt][nt][2], acc[mt][nt][3],
                            af[0], af[1], af[2], af[3], bf[nt][0], bf[nt][1]);
            }
        }
        __syncthreads();
    }

    // epilogue (accum layout: c0,c1 = row g cols 2tg,2tg+1; c2,c3 = row g+8)
    #pragma unroll
    for (int mt = 0; mt < 4; mt++) {
        int rA = row0 + mbase + mt * 16 + g;
        int rB = rA + 8;
        #pragma unroll
        for (int nt = 0; nt < 4; nt++) {
            int col = col0 + nbase + nt * 8 + tg * 2;
            float2 bv = *(const float2*)&bias[col];
            float v0 = acc[mt][nt][0] + bv.x;
            float v1 = acc[mt][nt][1] + bv.y;
            float v2 = acc[mt][nt][2] + bv.x;
            float v3 = acc[mt][nt][3] + bv.y;
            if (mode == 1) {
                v0 = gelu_tanh(v0); v1 = gelu_tanh(v1);
                v2 = gelu_tanh(v2); v3 = gelu_tanh(v3);
            }
            if (mode == 2) {
                if (rA < M) {
                    int bb = rA / rpb;
                    float2 gg = *(const float2*)&gate[(size_t)bb * 6144 + gofs + col];
                    float2 rr = *(const float2*)&res[(size_t)rA * N + col];
                    *(float2*)((float*)C + (size_t)rA * N + col) =
                        make_float2(rr.x + gg.x * v0, rr.y + gg.y * v1);
                }
                if (rB < M) {
                    int bb = rB / rpb;
                    float2 gg = *(const float2*)&gate[(size_t)bb * 6144 + gofs + col];
                    float2 rr = *(const float2*)&res[(size_t)rB * N + col];
                    *(float2*)((float*)C + (size_t)rB * N + col) =
                        make_float2(rr.x + gg.x * v2, rr.y + gg.y * v3);
                }
            } else {
                if (rA < M) {
                    __half2 h = __floats2half2_rn(v0, v1);
                    *(__half2*)((__half*)C + (size_t)rA * N + col) = h;
                }
                if (rB < M) {
                    __half2 h = __floats2half2_rn(v2, v3);
                    *(__half2*)((__half*)C + (size_t)rB * N + col) = h;
                }
            }
        }
    }
}

// ---------------- fp16 mma.sync joint flash attention ----------------------------
__global__ void attn_kernel(const __half* __restrict__ qkvx,
                            const __half* __restrict__ qkvc,
                            __half* __restrict__ out) {
    __shared__ __half Qs[64][72];
    __shared__ __half Ks[2][32][72];
    __shared__ __half Vs[2][32][72];

    const int qt = blockIdx.x, h = blockIdx.y, b = blockIdx.z;
    const int tid = threadIdx.x;
    const int lane = tid & 31, wid = tid >> 5;
    const int g = lane >> 2, tg = lane & 3;
    const int rlm = (lane & 7) + ((lane >> 3) & 1) * 8;
    const int clm = (lane >> 4) * 8;
    const int rk = (lane & 7) + ((lane >> 4) << 3);
    const int ck = ((lane >> 3) & 1) * 8;
    const int q0 = qt * 64;

    auto load_kv = [&](int kt, int st) {
        #pragma unroll
        for (int i = 0; i < 2; i++) {
            int c = i * 128 + tid;
            int r = c >> 3, q = c & 7;
            int key = kt * 32 + r;
            bool v = key < S_TOT;
            const __half* rp = qkvx;
            if (v) rp = (key < NN) ? (qkvx + (size_t)(b * NN + key) * 3072)
                                   : (qkvc + (size_t)(b * NC + (key - NN)) * 3072);
            cp16(&Ks[st][r][q * 8], rp + 1024 + h * HD + q * 8, v);
            cp16(&Vs[st][r][q * 8], rp + 2048 + h * HD + q * 8, v);
        }
        asm volatile("cp.async.commit_group;");
    };

    #pragma unroll
    for (int i = 0; i < 4; i++) {
        int c = i * 128 + tid;
        int r = c >> 3, q = c & 7;
        int qi = q0 + r;
        bool v = qi < S_TOT;
        const __half* rp = qkvx;
        if (v) rp = (qi < NN) ? (qkvx + (size_t)(b * NN + qi) * 3072)
                              : (qkvc + (size_t)(b * NC + (qi - NN)) * 3072);
        cp16(&Qs[r][q * 8], rp + h * HD + q * 8, v);
    }
    load_kv(0, 0);
    asm volatile("cp.async.wait_group 0;");
    __syncthreads();

    uint32_t qf[4][4];
    {
        const __half2 sc = __floats2half2_rn(0.125f, 0.125f);
        int r0 = wid * 16 + rlm;
        #pragma unroll
        for (int ks = 0; ks < 4; ks++) {
            ldsm4(qf[ks], (uint32_t)__cvta_generic_to_shared(&Qs[r0][ks * 16 + clm]));
            #pragma unroll
            for (int i = 0; i < 4; i++) {
                __half2 hv = *(__half2*)&qf[ks][i];
                hv = __hmul2(hv, sc);
                qf[ks][i] = *(uint32_t*)&hv;
            }
        }
    }

    float o[8][4];
    #pragma unroll
    for (int nt = 0; nt < 8; nt++)
        #pragma unroll
        for (int i = 0; i < 4; i++) o[nt][i] = 0.f;
    float m0 = -1e30f, m1 = -1e30f, l0 = 0.f, l1 = 0.f;

    const int nkt = (S_TOT + 31) / 32;

    for (int kt = 0; kt < nkt; kt++) {
        if (kt + 1 < nkt) {
            load_kv(kt + 1, (kt + 1) & 1);
            asm volatile("cp.async.wait_group 1;");
        } else {
            asm volatile("cp.async.wait_group 0;");
        }
        __syncthreads();
        const int s = kt & 1;

        float sa[4][4];
        #pragma unroll
        for (int nt = 0; nt < 4; nt++)
            #pragma unroll
            for (int i = 0; i < 4; i++) sa[nt][i] = 0.f;
        #pragma unroll
        for (int ks = 0; ks < 4; ks++) {
            #pragma unroll
            for (int p = 0; p < 2; p++) {
                uint32_t kb[4];
                ldsm4(kb, (uint32_t)__cvta_generic_to_shared(
                    &Ks[s][p * 16 + rk][ks * 16 + ck]));
                mma_f16(sa[2 * p][0], sa[2 * p][1], sa[2 * p][2], sa[2 * p][3],
                        qf[ks][0], qf[ks][1], qf[ks][2], qf[ks][3], kb[0], kb[1]);
                mma_f16(sa[2 * p + 1][0], sa[2 * p + 1][1], sa[2 * p + 1][2], sa[2 * p + 1][3],
                        qf[ks][0], qf[ks][1], qf[ks][2], qf[ks][3], kb[2], kb[3]);
            }
        }

        #pragma unroll
        for (int nt = 0; nt < 4; nt++) {
            int k0 = kt * 32 + nt * 8 + 2 * tg;
            if (k0 >= S_TOT) { sa[nt][0] = -1e30f; sa[nt][2] = -1e30f; }
            if (k0 + 1 >= S_TOT) { sa[nt][1] = -1e30f; sa[nt][3] = -1e30f; }
        }

        float mx0 = -1e30f, mx1 = -1e30f;
        #pragma unroll
        for (int nt = 0; nt < 4; nt++) {
            mx0 = fmaxf(mx0, fmaxf(sa[nt][0], sa[nt][1]));
            mx1 = fmaxf(mx1, fmaxf(sa[nt][2], sa[nt][3]));
        }
        mx0 = fmaxf(mx0, __shfl_xor_sync(0xffffffffu, mx0, 1));
        mx0 = fmaxf(mx0, __shfl_xor_sync(0xffffffffu, mx0, 2));
        mx1 = fmaxf(mx1, __shfl_xor_sync(0xffffffffu, mx1, 1));
        mx1 = fmaxf(mx1, __shfl_xor_sync(0xffffffffu, mx1, 2));
        float mn0 = fmaxf(m0, mx0), mn1 = fmaxf(m1, mx1);
        float sc0 = __expf(m0 - mn0), sc1 = __expf(m1 - mn1);
        float sum0 = 0.f, sum1 = 0.f;
        #pragma unroll
        for (int nt = 0; nt < 4; nt++) {
            sa[nt][0] = __expf(sa[nt][0] - mn0);
            sa[nt][1] = __expf(sa[nt][1] - mn0);
            sa[nt][2] = __expf(sa[nt][2] - mn1);
            sa[nt][3] = __expf(sa[nt][3] - mn1);
            sum0 += sa[nt][0] + sa[nt][1];
            sum1 += sa[nt][2] + sa[nt][3];
        }
        sum0 += __shfl_xor_sync(0xffffffffu, sum0, 1);
        sum0 += __shfl_xor_sync(0xffffffffu, sum0, 2);
        sum1 += __shfl_xor_sync(0xffffffffu, sum1, 1);
        sum1 += __shfl_xor_sync(0xffffffffu, sum1, 2);
        l0 = l0 * sc0 + sum0;
        l1 = l1 * sc1 + sum1;
        m0 = mn0; m1 = mn1;
        #pragma unroll
        for (int nt = 0; nt < 8; nt++) {
            o[nt][0] *= sc0; o[nt][1] *= sc0;
            o[nt][2] *= sc1; o[nt][3] *= sc1;
        }

        uint32_t pf[2][4];
        #pragma unroll
        for (int k2 = 0; k2 < 2; k2++) {
            pf[k2][0] = pk_f16(sa[2 * k2][0], sa[2 * k2][1]);
            pf[k2][1] = pk_f16(sa[2 * k2][2], sa[2 * k2][3]);
            pf[k2][2] = pk_f16(sa[2 * k2 + 1][0], sa[2 * k2 + 1][1]);
            pf[k2][3] = pk_f16(sa[2 * k2 + 1][2], sa[2 * k2 + 1][3]);
        }
        #pragma unroll
        for (int k2 = 0; k2 < 2; k2++) {
            #pragma unroll
            for (int p = 0; p < 4; p++) {
                uint32_t vb[4];
                ldsm4t(vb, (uint32_t)__cvta_generic_to_shared(
                    &Vs[s][k2 * 16 + rlm][p * 16 + clm]));
                mma_f16(o[2 * p][0], o[2 * p][1], o[2 * p][2], o[2 * p][3],
                        pf[k2][0], pf[k2][1], pf[k2][2], pf[k2][3], vb[0], vb[1]);
                mma_f16(o[2 * p + 1][0], o[2 * p + 1][1], o[2 * p + 1][2], o[2 * p + 1][3],
                        pf[k2][0], pf[k2][1], pf[k2][2], pf[k2][3], vb[2], vb[3]);
            }
        }
        __syncthreads();
    }

    float inv0 = 1.0f / l0, inv1 = 1.0f / l1;
    int r0 = q0 + wid * 16 + g;
    int r1 = r0 + 8;
    #pragma unroll
    for (int nt = 0; nt < 8; nt++) {
        int col = h * HD + nt * 8 + 2 * tg;
        if (r0 < S_TOT) {
            int rowg = (r0 < NN) ? (b * NN + r0) : (XROWS + b * NC + (r0 - NN));
            *(__half2*)&out[(size_t)rowg * DD + col] =
                __floats2half2_rn(o[nt][0] * inv0, o[nt][1] * inv0);
        }
        if (r1 < S_TOT) {
            int rowg = (r1 < NN) ? (b * NN + r1) : (XROWS + b * NC + (r1 - NN));
            *(__half2*)&out[(size_t)rowg * DD + col] =
                __floats2half2_rn(o[nt][2] * inv1, o[nt][3] * inv1);
        }
    }
}

// ---------------- launcher ----------------
extern "C" void kernel_launch(void* const* d_in, const int* in_sizes, int n_in,
                              void* d_out, int out_size) {
    const float* x       = (const float*)d_in[0];
    const float* cond    = (const float*)d_in[1];
    const float* c       = (const float*)d_in[2];
    const float* W_ada   = (const float*)d_in[3];
    const float* b_ada   = (const float*)d_in[4];
    const float* W_ada_c = (const float*)d_in[5];
    const float* b_ada_c = (const float*)d_in[6];
    const float* W_qkv   = (const float*)d_in[7];
    const float* b_qkv   = (const float*)d_in[8];
    const float* W_proj  = (const float*)d_in[9];
    const float* b_proj  = (const float*)d_in[10];
    const float* W_qkv_c = (const float*)d_in[11];
    const float* b_qkv_c = (const float*)d_in[12];
    const float* W_proj_c= (const float*)d_in[13];
    const float* b_proj_c= (const float*)d_in[14];
    const float* W_fc1   = (const float*)d_in[15];
    const float* b_fc1   = (const float*)d_in[16];
    const float* W_fc2   = (const float*)d_in[17];
    const float* b_fc2   = (const float*)d_in[18];
    const float* W_fc1_c = (const float*)d_in[19];
    const float* b_fc1_c = (const float*)d_in[20];
    const float* W_fc2_c = (const float*)d_in[21];
    const float* b_fc2_c = (const float*)d_in[22];
    float* out = (float*)d_out;

    float *adaA, *adaC, *xmid, *cmid;
    __half *xt, *qkvx, *qkvc, *attn, *hx, *hc;
    __half *wqkv, *wqkvc, *wproj, *wprojc, *wfc1, *wfc1c, *wfc2, *wfc2c;
    cudaGetSymbolAddress((void**)&adaA, g_adaA);
    cudaGetSymbolAddress((void**)&adaC, g_adaC);
    cudaGetSymbolAddress((void**)&xmid, g_xmid);
    cudaGetSymbolAddress((void**)&cmid, g_cmid);
    cudaGetSymbolAddress((void**)&xt,   h_xt);
    cudaGetSymbolAddress((void**)&qkvx, h_qkvx);
    cudaGetSymbolAddress((void**)&qkvc, h_qkvc);
    cudaGetSymbolAddress((void**)&attn, h_attn);
    cudaGetSymbolAddress((void**)&hx,   h_hx);
    cudaGetSymbolAddress((void**)&hc,   h_hc);
    cudaGetSymbolAddress((void**)&wqkv, h_Wqkv);
    cudaGetSymbolAddress((void**)&wqkvc,h_Wqkvc);
    cudaGetSymbolAddress((void**)&wproj,h_Wproj);
    cudaGetSymbolAddress((void**)&wprojc,h_Wprojc);
    cudaGetSymbolAddress((void**)&wfc1, h_Wfc1);
    cudaGetSymbolAddress((void**)&wfc1c,h_Wfc1c);
    cudaGetSymbolAddress((void**)&wfc2, h_Wfc2);
    cudaGetSymbolAddress((void**)&wfc2c,h_Wfc2c);

    // one fused weight convert launch (8 segments, grid-stride)
    CvtArgs ca;
    ca.seg[0] = { W_qkv,   wqkv,  DD * 3 * DD };
    ca.seg[1] = { W_qkv_c, wqkvc, DD * 3 * DD };
    ca.seg[2] = { W_proj,  wproj, DD * DD };
    ca.seg[3] = { W_proj_c,wprojc,DD * DD };
    ca.seg[4] = { W_fc1,   wfc1,  DD * DFF };
    ca.seg[5] = { W_fc1_c, wfc1c, DD * DFF };
    ca.seg[6] = { W_fc2,   wfc2,  DFF * DD };
    ca.seg[7] = { W_fc2_c, wfc2c, DFF * DD };
    f2h_all_kernel<<<dim3(296, 8), 256>>>(ca);

    const __half* xtc = xt + (size_t)XROWS * DD;
    const __half* attc = attn + (size_t)XROWS * DD;
    const int NY1 = XROWS / 128;                 // 32
    const int NY2 = (CROWS + 127) / 128;         // 3

    // 1. adaLN
    ada_kernel<<<dim3(6144 / 256, 2), 256>>>(c, W_ada, b_ada, W_ada_c, b_ada_c, adaA, adaC);
    // 2. LN + modulate (MSA) -> fp16
    ln_mod_kernel<<<TROWS, 256>>>(x, cond, adaA, adaC, 0, xt);
    // 3. fused QKV GEMMs -> fp16 qkv
    gemm_f16_fused<<<dim3(3072 / 128, NY1 + NY2), 256>>>(
        xt, wqkv, b_qkv, qkvx, XROWS,
        xtc, wqkvc, b_qkv_c, qkvc, CROWS,
        3072, 1024, NY1, nullptr, nullptr, 1, nullptr, nullptr, 1, 0, 0);
    // 4. joint attention -> fp16
    attn_kernel<<<dim3((S_TOT + 63) / 64, HH, BB), 128>>>(qkvx, qkvc, attn);
    // 5. fused proj + gated residual -> fp32 xmid/cmid
    gemm_f16_fused<<<dim3(1024 / 128, NY1 + NY2), 256>>>(
        attn, wproj, b_proj, xmid, XROWS,
        attc, wprojc, b_proj_c, cmid, CROWS,
        1024, 1024, NY1, x, adaA, NN, cond, adaC, NC, 2048, 2);
    // 6. LN + modulate (MLP) -> fp16
    ln_mod_kernel<<<TROWS, 256>>>(xmid, cmid, adaA, adaC, 3072, xt);
    // 7. fused fc1 + GELU -> fp16 hidden
    gemm_f16_fused<<<dim3(DFF / 128, NY1 + NY2), 256>>>(
        xt, wfc1, b_fc1, hx, XROWS,
        xtc, wfc1c, b_fc1_c, hc, CROWS,
        DFF, 1024, NY1, nullptr, nullptr, 1, nullptr, nullptr, 1, 0, 1);
    // 8. fused fc2 + gated residual -> fp32 d_out
    gemm_f16_fused<<<dim3(1024 / 128, NY1 + NY2), 256>>>(
        hx, wfc2, b_fc2, out, XROWS,
        hc, wfc2c, b_fc2_c, out + (size_t)XROWS * DD, CROWS,
        1024, DFF, NY1, xmid, adaA, NN, cmid, adaC, NC, 5120, 2);
}